// round 1
// baseline (speedup 1.0000x reference)
#include <cuda_runtime.h>
#include <math.h>

#define N_   4
#define S_   2048
#define D_   768
#define H_   12
#define HD_  64
#define DFF_ 3072
#define NS_  (N_ * S_)

// ---------------- scratch (static device globals; no allocations) ----------
__device__ float g_q  [N_ * H_ * S_ * HD_];   // 25 MB
__device__ float g_k  [N_ * H_ * S_ * HD_];
__device__ float g_v  [N_ * H_ * S_ * HD_];
__device__ float g_ctx[NS_ * D_];
__device__ float g_t1 [NS_ * D_];
__device__ float g_n1 [NS_ * D_];
__device__ float g_ff [NS_ * DFF_];           // 100 MB
__device__ float g_f2 [NS_ * D_];
__device__ int   g_mask64;

// ---------------- mask dtype detector --------------------------------------
// If the mask tensor is int64 (little-endian, values 0/1), every odd 32-bit
// word within the first 8192 words is zero. If int32, odd words are random
// 0/1 bits -> essentially impossible to be all zero (P = 2^-4096).
__global__ void detect_mask(const int* __restrict__ w)
{
    __shared__ int anynz;
    if (threadIdx.x == 0) anynz = 0;
    __syncthreads();
    int loc = 0;
    for (int i = threadIdx.x; i < 4096; i += 256)
        if (w[2 * i + 1] != 0) loc = 1;
    if (loc) atomicExch(&anynz, 1);
    __syncthreads();
    if (threadIdx.x == 0) g_mask64 = anynz ? 0 : 1;
}

// ---------------- generic SGEMM: C = A[M,K] @ B[Nc,K]^T ---------------------
// MODE 0: plain row-major store
// MODE 1: QKV scatter into [N,H,S,HD]
// MODE 2: exact GELU epilogue
template<int MODE>
__global__ __launch_bounds__(256) void sgemm(const float* __restrict__ A,
                                             const float* __restrict__ B,
                                             float* __restrict__ C,
                                             int M, int Nc, int K)
{
    __shared__ float As[8][128];
    __shared__ float Bs[8][128];
    const int tid = threadIdx.x;
    const int bm  = blockIdx.y * 128;
    const int bn  = blockIdx.x * 128;
    const int lr  = tid >> 1;           // 0..127
    const int lk  = (tid & 1) * 4;      // 0 or 4
    const float* ap = A + (size_t)(bm + lr) * K + lk;
    const float* bp = B + (size_t)(bn + lr) * K + lk;
    const int tr = (tid >> 4) * 8;
    const int tc = (tid & 15) * 8;

    float acc[8][8];
#pragma unroll
    for (int i = 0; i < 8; ++i)
#pragma unroll
        for (int j = 0; j < 8; ++j) acc[i][j] = 0.f;

    for (int k0 = 0; k0 < K; k0 += 8) {
        float4 av = *(const float4*)ap; ap += 8;
        float4 bv = *(const float4*)bp; bp += 8;
        __syncthreads();
        As[lk + 0][lr] = av.x; As[lk + 1][lr] = av.y;
        As[lk + 2][lr] = av.z; As[lk + 3][lr] = av.w;
        Bs[lk + 0][lr] = bv.x; Bs[lk + 1][lr] = bv.y;
        Bs[lk + 2][lr] = bv.z; Bs[lk + 3][lr] = bv.w;
        __syncthreads();
#pragma unroll
        for (int kk = 0; kk < 8; ++kk) {
            float ar[8], br[8];
            *(float4*)(ar)     = *(const float4*)&As[kk][tr];
            *(float4*)(ar + 4) = *(const float4*)&As[kk][tr + 4];
            *(float4*)(br)     = *(const float4*)&Bs[kk][tc];
            *(float4*)(br + 4) = *(const float4*)&Bs[kk][tc + 4];
#pragma unroll
            for (int i = 0; i < 8; ++i)
#pragma unroll
                for (int j = 0; j < 8; ++j)
                    acc[i][j] += ar[i] * br[j];
        }
    }

#pragma unroll
    for (int i = 0; i < 8; ++i) {
        const int row = bm + tr + i;
#pragma unroll
        for (int j = 0; j < 8; ++j) {
            const int col = bn + tc + j;
            float v = acc[i][j];
            if (MODE == 1) {
                // row = b*S + s ; col = h*HD + hd  ->  [((b*H+h)*S + s)*HD + hd]
                const int bb = row >> 11, sr = row & 2047;
                const int hh = col >> 6,  hd = col & 63;
                C[(((size_t)(bb * H_ + hh) << 11) + sr) * HD_ + hd] = v;
            } else if (MODE == 2) {
                C[(size_t)row * Nc + col] =
                    0.5f * v * (1.f + erff(v * 0.70710678118654752f));
            } else {
                C[(size_t)row * Nc + col] = v;
            }
        }
    }
}

// ---------------- flash attention ------------------------------------------
// One block = one (b,h) and 64 queries; 64 threads, 1 query/thread.
// Online softmax with 16-key sub-tiles. Scale 1/sqrt(64)=0.125.
__global__ __launch_bounds__(64) void flash_attn(const float* __restrict__ Q,
                                                 const float* __restrict__ K,
                                                 const float* __restrict__ V,
                                                 const int* __restrict__ mask,
                                                 float* __restrict__ ctx)
{
    __shared__ float Ks[64 * 64];
    __shared__ float Vs[64 * 64];
    __shared__ float madd[64];
    const int tid = threadIdx.x;
    const int q0  = blockIdx.x * 64;
    const int h   = blockIdx.y, b = blockIdx.z;
    const int is64 = g_mask64;
    const size_t headoff = (size_t)(b * H_ + h) * S_ * HD_;

    const float4* qp = (const float4*)(Q + headoff + (size_t)(q0 + tid) * HD_);
    float4 q4[16], o4[16];
#pragma unroll
    for (int i = 0; i < 16; ++i) {
        q4[i] = qp[i];
        o4[i] = make_float4(0.f, 0.f, 0.f, 0.f);
    }
    float m = -1e29f, l = 0.f;   // init m > masked-score (-1e30) so fully-masked
                                 // tiles contribute exp(-1e30+1e29) = 0.
    const float4* kb = (const float4*)(K + headoff);
    const float4* vb = (const float4*)(V + headoff);

#pragma unroll 1
    for (int k0 = 0; k0 < S_; k0 += 64) {
        __syncthreads();
#pragma unroll
        for (int i = 0; i < 16; ++i) {
            const int f = i * 64 + tid;          // coalesced float4 index
            ((float4*)Ks)[f] = kb[k0 * 16 + f];
            ((float4*)Vs)[f] = vb[k0 * 16 + f];
        }
        {
            const int kk = b * S_ + k0 + tid;
            const int mv = is64 ? mask[2 * kk] : mask[kk];
            madd[tid] = (mv == 0) ? -1e30f : 0.f;
        }
        __syncthreads();

#pragma unroll 1
        for (int jj = 0; jj < 64; jj += 16) {
            float sv[16];
#pragma unroll
            for (int j = 0; j < 16; ++j) {
                const float4* kr = (const float4*)(Ks + (jj + j) * 64);
                float a0 = 0.f, a1 = 0.f, a2 = 0.f, a3 = 0.f;
#pragma unroll
                for (int d = 0; d < 16; ++d) {
                    const float4 kk4 = kr[d];
                    a0 += q4[d].x * kk4.x; a1 += q4[d].y * kk4.y;
                    a2 += q4[d].z * kk4.z; a3 += q4[d].w * kk4.w;
                }
                sv[j] = ((a0 + a1) + (a2 + a3)) * 0.125f + madd[jj + j];
            }
            float tm = sv[0];
#pragma unroll
            for (int j = 1; j < 16; ++j) tm = fmaxf(tm, sv[j]);
            const float mn    = fmaxf(m, tm);
            const float alpha = __expf(m - mn);
            m = mn;
            l *= alpha;
#pragma unroll
            for (int d = 0; d < 16; ++d) {
                o4[d].x *= alpha; o4[d].y *= alpha;
                o4[d].z *= alpha; o4[d].w *= alpha;
            }
#pragma unroll
            for (int j = 0; j < 16; ++j) {
                const float p = __expf(sv[j] - m);
                l += p;
                const float4* vr = (const float4*)(Vs + (jj + j) * 64);
#pragma unroll
                for (int d = 0; d < 16; ++d) {
                    const float4 vv = vr[d];
                    o4[d].x += p * vv.x; o4[d].y += p * vv.y;
                    o4[d].z += p * vv.z; o4[d].w += p * vv.w;
                }
            }
        }
    }

    const float inv = 1.f / l;
    // write directly in [N,S,D] layout for the Wo GEMM
    float4* op = (float4*)(ctx + (size_t)(b * S_ + q0 + tid) * D_ + h * HD_);
#pragma unroll
    for (int d = 0; d < 16; ++d) {
        const float4 w = o4[d];
        op[d] = make_float4(w.x * inv, w.y * inv, w.z * inv, w.w * inv);
    }
}

// ---------------- residual + LayerNorm -------------------------------------
__global__ __launch_bounds__(256) void ln_kernel(const float* __restrict__ A,
                                                 const float* __restrict__ R,
                                                 const float* __restrict__ g,
                                                 const float* __restrict__ bta,
                                                 float* __restrict__ out)
{
    const int row = blockIdx.x, tid = threadIdx.x;
    const float* a = A + (size_t)row * D_;
    const float* r = R + (size_t)row * D_;
    const float v0 = a[tid]       + r[tid];
    const float v1 = a[tid + 256] + r[tid + 256];
    const float v2 = a[tid + 512] + r[tid + 512];
    float s = v0 + v1 + v2;
    float q = v0 * v0 + v1 * v1 + v2 * v2;
#pragma unroll
    for (int o = 16; o > 0; o >>= 1) {
        s += __shfl_xor_sync(0xffffffffu, s, o);
        q += __shfl_xor_sync(0xffffffffu, q, o);
    }
    __shared__ float ss[8], sq[8], stats[2];
    const int wid = tid >> 5;
    if ((tid & 31) == 0) { ss[wid] = s; sq[wid] = q; }
    __syncthreads();
    if (tid == 0) {
        float S = 0.f, Q = 0.f;
#pragma unroll
        for (int w = 0; w < 8; ++w) { S += ss[w]; Q += sq[w]; }
        const float mean = S * (1.f / 768.f);
        const float var  = Q * (1.f / 768.f) - mean * mean;
        stats[0] = mean;
        stats[1] = rsqrtf(var + 1e-5f);
    }
    __syncthreads();
    const float mean = stats[0], rstd = stats[1];
    float* o = out + (size_t)row * D_;
    o[tid]       = (v0 - mean) * rstd * g[tid]       + bta[tid];
    o[tid + 256] = (v1 - mean) * rstd * g[tid + 256] + bta[tid + 256];
    o[tid + 512] = (v2 - mean) * rstd * g[tid + 512] + bta[tid + 512];
}

// ---------------- launch -----------------------------------------------------
extern "C" void kernel_launch(void* const* d_in, const int* in_sizes, int n_in,
                              void* d_out, int out_size)
{
    (void)in_sizes; (void)n_in; (void)out_size;
    const float* x  = (const float*)d_in[0];
    const int*   mk = (const int*)d_in[1];
    const float* Wq = (const float*)d_in[2];
    const float* Wk = (const float*)d_in[3];
    const float* Wv = (const float*)d_in[4];
    const float* Wo = (const float*)d_in[5];
    const float* W1 = (const float*)d_in[6];
    const float* W2 = (const float*)d_in[7];
    const float* lg = (const float*)d_in[8];
    const float* lb = (const float*)d_in[9];
    float* out = (float*)d_out;

    float *q, *k, *v, *ctx, *t1, *n1, *ff, *f2;
    cudaGetSymbolAddress((void**)&q,   g_q);
    cudaGetSymbolAddress((void**)&k,   g_k);
    cudaGetSymbolAddress((void**)&v,   g_v);
    cudaGetSymbolAddress((void**)&ctx, g_ctx);
    cudaGetSymbolAddress((void**)&t1,  g_t1);
    cudaGetSymbolAddress((void**)&n1,  g_n1);
    cudaGetSymbolAddress((void**)&ff,  g_ff);
    cudaGetSymbolAddress((void**)&f2,  g_f2);

    detect_mask<<<1, 256>>>(mk);

    const dim3 gp(D_ / 128, NS_ / 128);       // (6, 64)
    sgemm<1><<<gp, 256>>>(x, Wq, q, NS_, D_, D_);
    sgemm<1><<<gp, 256>>>(x, Wk, k, NS_, D_, D_);
    sgemm<1><<<gp, 256>>>(x, Wv, v, NS_, D_, D_);

    flash_attn<<<dim3(S_ / 64, H_, N_), 64>>>(q, k, v, mk, ctx);

    sgemm<0><<<gp, 256>>>(ctx, Wo, t1, NS_, D_, D_);
    ln_kernel<<<NS_, 256>>>(x, t1, lg, lb, n1);

    sgemm<2><<<dim3(DFF_ / 128, NS_ / 128), 256>>>(n1, W1, ff, NS_, DFF_, D_);
    sgemm<0><<<gp, 256>>>(ff, W2, f2, NS_, D_, DFF_);
    ln_kernel<<<NS_, 256>>>(n1, f2, lg, lb, out);
}

// round 3
// speedup vs baseline: 1.6277x; 1.6277x over previous
#include <cuda_runtime.h>
#include <cuda_bf16.h>
#include <math.h>
#include <stdint.h>

#define N_   4
#define S_   2048
#define D_   768
#define H_   12
#define HD_  64
#define DFF_ 3072
#define NS_  (N_ * S_)

// ======================= PTX helpers (family-agnostic, sm_80+) ==============
__device__ __forceinline__ uint32_t smem_u32(const void* p) {
    uint32_t a;
    asm("{ .reg .u64 t; cvta.to.shared.u64 t, %1; cvt.u32.u64 %0, t; }"
        : "=r"(a) : "l"(p));
    return a;
}
__device__ __forceinline__ void ldsm4(uint32_t r[4], uint32_t a) {
    asm volatile("ldmatrix.sync.aligned.m8n8.x4.shared.b16 {%0,%1,%2,%3}, [%4];"
        : "=r"(r[0]), "=r"(r[1]), "=r"(r[2]), "=r"(r[3]) : "r"(a));
}
__device__ __forceinline__ void mma16816(float c[4], const uint32_t a[4],
                                         const uint32_t b[2]) {
    asm volatile("mma.sync.aligned.m16n8k16.row.col.f32.bf16.bf16.f32 "
        "{%0,%1,%2,%3}, {%4,%5,%6,%7}, {%8,%9}, {%0,%1,%2,%3};"
        : "+f"(c[0]), "+f"(c[1]), "+f"(c[2]), "+f"(c[3])
        : "r"(a[0]), "r"(a[1]), "r"(a[2]), "r"(a[3]), "r"(b[0]), "r"(b[1]));
}
__device__ __forceinline__ void cpasync16(uint32_t dst, const void* src) {
    asm volatile("cp.async.cg.shared.global [%0], [%1], 16;" :: "r"(dst), "l"(src));
}
#define CP_COMMIT() asm volatile("cp.async.commit_group;" ::: "memory")
#define CP_WAIT(n)  asm volatile("cp.async.wait_group %0;" :: "n"(n) : "memory")

// ======================= scratch ============================================
__device__ __nv_bfloat16 g_xh [NS_ * D_],  g_xl [NS_ * D_];
__device__ __nv_bfloat16 g_wqkvh[3 * D_ * D_], g_wqkvl[3 * D_ * D_];
__device__ __nv_bfloat16 g_woh[D_ * D_],   g_wol[D_ * D_];
__device__ __nv_bfloat16 g_w1h[DFF_ * D_], g_w1l[DFF_ * D_];
__device__ __nv_bfloat16 g_w2h[D_ * DFF_], g_w2l[D_ * DFF_];
__device__ float g_q  [N_ * H_ * S_ * HD_];
__device__ float g_k  [N_ * H_ * S_ * HD_];
__device__ float g_v  [N_ * H_ * S_ * HD_];
__device__ __nv_bfloat16 g_ctxh[NS_ * D_], g_ctxl[NS_ * D_];
__device__ float g_t1 [NS_ * D_];
__device__ float g_n1 [NS_ * D_];
__device__ __nv_bfloat16 g_n1h[NS_ * D_],  g_n1l[NS_ * D_];
__device__ __nv_bfloat16 g_ffh[NS_ * DFF_], g_ffl[NS_ * DFF_];
__device__ float g_f2 [NS_ * D_];
__device__ int   g_mask64;

// ======================= mask dtype detector ================================
__global__ void detect_mask(const int* __restrict__ w)
{
    __shared__ int anynz;
    if (threadIdx.x == 0) anynz = 0;
    __syncthreads();
    int loc = 0;
    for (int i = threadIdx.x; i < 4096; i += 256)
        if (w[2 * i + 1] != 0) loc = 1;
    if (loc) atomicExch(&anynz, 1);
    __syncthreads();
    if (threadIdx.x == 0) g_mask64 = anynz ? 0 : 1;
}

// ======================= fp32 -> bf16 hi/lo split ===========================
__global__ __launch_bounds__(256) void convert_hl(const float* __restrict__ src,
                                                  __nv_bfloat16* __restrict__ h,
                                                  __nv_bfloat16* __restrict__ l,
                                                  int n)
{
    for (int i = blockIdx.x * 256 + threadIdx.x; i < n; i += gridDim.x * 256) {
        const float v = src[i];
        const __nv_bfloat16 hi = __float2bfloat16(v);
        h[i] = hi;
        l[i] = __float2bfloat16(v - __bfloat162float(hi));
    }
}

// ======================= split-bf16 HMMA GEMM ===============================
// C = A[M,K] @ B[Nc,K]^T via Ah*Bh + Al*Bh + Ah*Bl  (fp32 accum in registers)
// MODE 0: plain fp32 store to C0
// MODE 1: QKV scatter (Nc=2304): segment 0/1/2 -> C0/C1/C2 in [N,H,S,HD]
// MODE 2: exact GELU, then bf16 hi/lo split store to Oh/Ol
#define KC 32
#define TILE_B  8192           // 128 rows x 32 bf16 = 8 KB
#define STAGE_B (4 * TILE_B)   // Ah, Al, Bh, Bl
#define GEMM_SMEM (2 * STAGE_B)

// swizzle: 16B-unit index u(row, c) = row*4 + (c ^ ((row>>1)&3)); byte = 16*u
__device__ __forceinline__ uint32_t swz_off(int row, int c) {
    return (uint32_t)((row * 4 + (c ^ ((row >> 1) & 3))) * 16);
}

template<int MODE>
__global__ __launch_bounds__(256) void gemm_mma(
    const __nv_bfloat16* __restrict__ Ah, const __nv_bfloat16* __restrict__ Al,
    const __nv_bfloat16* __restrict__ Bh, const __nv_bfloat16* __restrict__ Bl,
    float* __restrict__ C0, float* __restrict__ C1, float* __restrict__ C2,
    __nv_bfloat16* __restrict__ Oh, __nv_bfloat16* __restrict__ Ol,
    int M, int Nc, int K)
{
    extern __shared__ char smem[];
    const uint32_t sb = smem_u32(smem);
    const int tid  = threadIdx.x;
    const int wid  = tid >> 5, lane = tid & 31;
    const int bm   = blockIdx.y * 128, bn = blockIdx.x * 128;
    const int wm   = (wid >> 1) * 32, wn = (wid & 1) * 64;

    // ---- cp.async mapping: each thread copies 2x16B per tile ----
    const int crow = tid >> 1;
    const int cc   = (tid & 1) * 2;
    const uint32_t d0 = swz_off(crow, cc);
    const uint32_t d1 = swz_off(crow, cc + 1);
    const __nv_bfloat16* gAh = Ah + (size_t)(bm + crow) * K + cc * 8;
    const __nv_bfloat16* gAl = Al + (size_t)(bm + crow) * K + cc * 8;
    const __nv_bfloat16* gBh = Bh + (size_t)(bn + crow) * K + cc * 8;
    const __nv_bfloat16* gBl = Bl + (size_t)(bn + crow) * K + cc * 8;

    // ---- ldmatrix per-lane offsets (k16 step toggles via ^32) ----
    const int ra = (lane & 7) | (((lane >> 3) & 1) << 3);
    const int ca = (lane >> 4) & 1;
    const uint32_t aoff = (uint32_t)(wm * 64) + swz_off(ra, ca);
    const int rb = (lane & 7) | (((lane >> 4) & 1) << 3);
    const int cb = (lane >> 3) & 1;
    const uint32_t boff = (uint32_t)(wn * 64) + swz_off(rb, cb);

    float acc[2][8][4];
#pragma unroll
    for (int mt = 0; mt < 2; ++mt)
#pragma unroll
        for (int nt = 0; nt < 8; ++nt)
#pragma unroll
            for (int e = 0; e < 4; ++e) acc[mt][nt][e] = 0.f;

    const int NCH = K / KC;

    auto load_stage = [&](int s, int k0) {
        const uint32_t base = sb + s * STAGE_B;
        cpasync16(base + 0 * TILE_B + d0, gAh + k0);
        cpasync16(base + 0 * TILE_B + d1, gAh + k0 + 8);
        cpasync16(base + 1 * TILE_B + d0, gAl + k0);
        cpasync16(base + 1 * TILE_B + d1, gAl + k0 + 8);
        cpasync16(base + 2 * TILE_B + d0, gBh + k0);
        cpasync16(base + 2 * TILE_B + d1, gBh + k0 + 8);
        cpasync16(base + 3 * TILE_B + d0, gBl + k0);
        cpasync16(base + 3 * TILE_B + d1, gBl + k0 + 8);
    };

    load_stage(0, 0);
    CP_COMMIT();

#pragma unroll 1
    for (int ch = 0; ch < NCH; ++ch) {
        if (ch + 1 < NCH) {
            load_stage((ch + 1) & 1, (ch + 1) * KC);
            CP_COMMIT();
            CP_WAIT(1);
        } else {
            CP_WAIT(0);
        }
        __syncthreads();
        const uint32_t base = sb + (ch & 1) * STAGE_B;

#pragma unroll
        for (int ks = 0; ks < 2; ++ks) {
            const uint32_t kx = ks ? 32u : 0u;
            uint32_t a_h[2][4], a_l[2][4], bfr[4][4];
            // Ah + Bh
            ldsm4(a_h[0], base + 0 * TILE_B + (aoff ^ kx));
            ldsm4(a_h[1], base + 0 * TILE_B + (aoff ^ kx) + 1024);
#pragma unroll
            for (int q = 0; q < 4; ++q)
                ldsm4(bfr[q], base + 2 * TILE_B + (boff ^ kx) + q * 1024);
#pragma unroll
            for (int mt = 0; mt < 2; ++mt)
#pragma unroll
                for (int q = 0; q < 4; ++q) {
                    mma16816(acc[mt][2 * q],     a_h[mt], &bfr[q][0]);
                    mma16816(acc[mt][2 * q + 1], a_h[mt], &bfr[q][2]);
                }
            // Al * Bh (Bh still resident)
            ldsm4(a_l[0], base + 1 * TILE_B + (aoff ^ kx));
            ldsm4(a_l[1], base + 1 * TILE_B + (aoff ^ kx) + 1024);
#pragma unroll
            for (int mt = 0; mt < 2; ++mt)
#pragma unroll
                for (int q = 0; q < 4; ++q) {
                    mma16816(acc[mt][2 * q],     a_l[mt], &bfr[q][0]);
                    mma16816(acc[mt][2 * q + 1], a_l[mt], &bfr[q][2]);
                }
            // Ah * Bl (reuse bfr regs)
#pragma unroll
            for (int q = 0; q < 4; ++q)
                ldsm4(bfr[q], base + 3 * TILE_B + (boff ^ kx) + q * 1024);
#pragma unroll
            for (int mt = 0; mt < 2; ++mt)
#pragma unroll
                for (int q = 0; q < 4; ++q) {
                    mma16816(acc[mt][2 * q],     a_h[mt], &bfr[q][0]);
                    mma16816(acc[mt][2 * q + 1], a_h[mt], &bfr[q][2]);
                }
        }
        __syncthreads();
    }

    // ---- epilogue ----
    const int g  = lane >> 2;
    const int tg = lane & 3;
#pragma unroll
    for (int mt = 0; mt < 2; ++mt) {
#pragma unroll
        for (int nt = 0; nt < 8; ++nt) {
            const int row = bm + wm + mt * 16 + g;
            const int col = bn + wn + nt * 8 + tg * 2;
            const float* c = acc[mt][nt];
            if (MODE == 0) {
                *(float2*)(C0 + (size_t)row * Nc + col) = make_float2(c[0], c[1]);
                *(float2*)(C0 + (size_t)(row + 8) * Nc + col) = make_float2(c[2], c[3]);
            } else if (MODE == 1) {
                const int seg = col / 768;
                const int cw  = col - seg * 768;
                const int h   = cw >> 6, hd = cw & 63;
                float* base = (seg == 0) ? C0 : ((seg == 1) ? C1 : C2);
                const int b0 = row >> 11, s0 = row & 2047;
                float* p0 = base + (((size_t)(b0 * H_ + h) << 11) + s0) * HD_ + hd;
                *(float2*)p0 = make_float2(c[0], c[1]);
                const int b1 = (row + 8) >> 11, s1 = (row + 8) & 2047;
                float* p1 = base + (((size_t)(b1 * H_ + h) << 11) + s1) * HD_ + hd;
                *(float2*)p1 = make_float2(c[2], c[3]);
            } else {
#pragma unroll
                for (int half = 0; half < 2; ++half) {
                    const int r = row + half * 8;
                    const float v0 = c[2 * half], v1 = c[2 * half + 1];
                    const float e0 = 0.5f * v0 * (1.f + erff(v0 * 0.70710678118654752f));
                    const float e1 = 0.5f * v1 * (1.f + erff(v1 * 0.70710678118654752f));
                    const __nv_bfloat16 h0 = __float2bfloat16(e0);
                    const __nv_bfloat16 h1 = __float2bfloat16(e1);
                    const size_t o = (size_t)r * Nc + col;
                    *(__nv_bfloat162*)(Oh + o) = __nv_bfloat162(h0, h1);
                    *(__nv_bfloat162*)(Ol + o) = __nv_bfloat162(
                        __float2bfloat16(e0 - __bfloat162float(h0)),
                        __float2bfloat16(e1 - __bfloat162float(h1)));
                }
            }
        }
    }
}

// ======================= flash attention (fp32) =============================
__global__ __launch_bounds__(64) void flash_attn(const float* __restrict__ Q,
                                                 const float* __restrict__ K,
                                                 const float* __restrict__ V,
                                                 const int* __restrict__ mask,
                                                 __nv_bfloat16* __restrict__ Oh,
                                                 __nv_bfloat16* __restrict__ Ol)
{
    __shared__ float Ks[64 * 64];
    __shared__ float Vs[64 * 64];
    __shared__ float madd[64];
    const int tid = threadIdx.x;
    const int q0  = blockIdx.x * 64;
    const int h   = blockIdx.y, b = blockIdx.z;
    const int is64 = g_mask64;
    const size_t headoff = (size_t)(b * H_ + h) * S_ * HD_;

    const float4* qp = (const float4*)(Q + headoff + (size_t)(q0 + tid) * HD_);
    float4 q4[16], o4[16];
#pragma unroll
    for (int i = 0; i < 16; ++i) {
        q4[i] = qp[i];
        o4[i] = make_float4(0.f, 0.f, 0.f, 0.f);
    }
    float m = -1e29f, l = 0.f;
    const float4* kb = (const float4*)(K + headoff);
    const float4* vb = (const float4*)(V + headoff);

#pragma unroll 1
    for (int k0 = 0; k0 < S_; k0 += 64) {
        __syncthreads();
#pragma unroll
        for (int i = 0; i < 16; ++i) {
            const int f = i * 64 + tid;
            ((float4*)Ks)[f] = kb[k0 * 16 + f];
            ((float4*)Vs)[f] = vb[k0 * 16 + f];
        }
        {
            const int kk = b * S_ + k0 + tid;
            const int mv = is64 ? mask[2 * kk] : mask[kk];
            madd[tid] = (mv == 0) ? -1e30f : 0.f;
        }
        __syncthreads();

#pragma unroll 1
        for (int jj = 0; jj < 64; jj += 16) {
            float sv[16];
#pragma unroll
            for (int j = 0; j < 16; ++j) {
                const float4* kr = (const float4*)(Ks + (jj + j) * 64);
                float a0 = 0.f, a1 = 0.f, a2 = 0.f, a3 = 0.f;
#pragma unroll
                for (int d = 0; d < 16; ++d) {
                    const float4 kk4 = kr[d];
                    a0 += q4[d].x * kk4.x; a1 += q4[d].y * kk4.y;
                    a2 += q4[d].z * kk4.z; a3 += q4[d].w * kk4.w;
                }
                sv[j] = ((a0 + a1) + (a2 + a3)) * 0.125f + madd[jj + j];
            }
            float tm = sv[0];
#pragma unroll
            for (int j = 1; j < 16; ++j) tm = fmaxf(tm, sv[j]);
            const float mn    = fmaxf(m, tm);
            const float alpha = __expf(m - mn);
            m = mn;
            l *= alpha;
#pragma unroll
            for (int d = 0; d < 16; ++d) {
                o4[d].x *= alpha; o4[d].y *= alpha;
                o4[d].z *= alpha; o4[d].w *= alpha;
            }
#pragma unroll
            for (int j = 0; j < 16; ++j) {
                const float p = __expf(sv[j] - m);
                l += p;
                const float4* vr = (const float4*)(Vs + (jj + j) * 64);
#pragma unroll
                for (int d = 0; d < 16; ++d) {
                    const float4 vv = vr[d];
                    o4[d].x += p * vv.x; o4[d].y += p * vv.y;
                    o4[d].z += p * vv.z; o4[d].w += p * vv.w;
                }
            }
        }
    }

    const float inv = 1.f / l;
    const size_t ob = (size_t)(b * S_ + q0 + tid) * D_ + h * HD_;
#pragma unroll
    for (int d = 0; d < 16; ++d) {
        float vals[4] = { o4[d].x * inv, o4[d].y * inv, o4[d].z * inv, o4[d].w * inv };
        __nv_bfloat16 hs[4], ls[4];
#pragma unroll
        for (int e = 0; e < 4; ++e) {
            hs[e] = __float2bfloat16(vals[e]);
            ls[e] = __float2bfloat16(vals[e] - __bfloat162float(hs[e]));
        }
        *(__nv_bfloat162*)(Oh + ob + d * 4)     = __nv_bfloat162(hs[0], hs[1]);
        *(__nv_bfloat162*)(Oh + ob + d * 4 + 2) = __nv_bfloat162(hs[2], hs[3]);
        *(__nv_bfloat162*)(Ol + ob + d * 4)     = __nv_bfloat162(ls[0], ls[1]);
        *(__nv_bfloat162*)(Ol + ob + d * 4 + 2) = __nv_bfloat162(ls[2], ls[3]);
    }
}

// ======================= residual + LayerNorm ===============================
template<bool WB>
__global__ __launch_bounds__(256) void ln_kernel(const float* __restrict__ A,
                                                 const float* __restrict__ R,
                                                 const float* __restrict__ g,
                                                 const float* __restrict__ bta,
                                                 float* __restrict__ out,
                                                 __nv_bfloat16* __restrict__ Oh,
                                                 __nv_bfloat16* __restrict__ Ol)
{
    const int row = blockIdx.x, tid = threadIdx.x;
    const float* a = A + (size_t)row * D_;
    const float* r = R + (size_t)row * D_;
    const float v0 = a[tid]       + r[tid];
    const float v1 = a[tid + 256] + r[tid + 256];
    const float v2 = a[tid + 512] + r[tid + 512];
    float s = v0 + v1 + v2;
    float q = v0 * v0 + v1 * v1 + v2 * v2;
#pragma unroll
    for (int o = 16; o > 0; o >>= 1) {
        s += __shfl_xor_sync(0xffffffffu, s, o);
        q += __shfl_xor_sync(0xffffffffu, q, o);
    }
    __shared__ float ss[8], sq[8], stats[2];
    const int wid = tid >> 5;
    if ((tid & 31) == 0) { ss[wid] = s; sq[wid] = q; }
    __syncthreads();
    if (tid == 0) {
        float S = 0.f, Q = 0.f;
#pragma unroll
        for (int w = 0; w < 8; ++w) { S += ss[w]; Q += sq[w]; }
        const float mean = S * (1.f / 768.f);
        const float var  = Q * (1.f / 768.f) - mean * mean;
        stats[0] = mean;
        stats[1] = rsqrtf(var + 1e-5f);
    }
    __syncthreads();
    const float mean = stats[0], rstd = stats[1];
    float* o = out + (size_t)row * D_;
    const float y0 = (v0 - mean) * rstd * g[tid]       + bta[tid];
    const float y1 = (v1 - mean) * rstd * g[tid + 256] + bta[tid + 256];
    const float y2 = (v2 - mean) * rstd * g[tid + 512] + bta[tid + 512];
    o[tid] = y0; o[tid + 256] = y1; o[tid + 512] = y2;
    if (WB) {
        const size_t ob = (size_t)row * D_;
        const float ys[3] = { y0, y1, y2 };
#pragma unroll
        for (int e = 0; e < 3; ++e) {
            const __nv_bfloat16 hh = __float2bfloat16(ys[e]);
            Oh[ob + tid + 256 * e] = hh;
            Ol[ob + tid + 256 * e] =
                __float2bfloat16(ys[e] - __bfloat162float(hh));
        }
    }
}

// ======================= launch =============================================
extern "C" void kernel_launch(void* const* d_in, const int* in_sizes, int n_in,
                              void* d_out, int out_size)
{
    (void)in_sizes; (void)n_in; (void)out_size;
    const float* x  = (const float*)d_in[0];
    const int*   mk = (const int*)d_in[1];
    const float* Wq = (const float*)d_in[2];
    const float* Wk = (const float*)d_in[3];
    const float* Wv = (const float*)d_in[4];
    const float* Wo = (const float*)d_in[5];
    const float* W1 = (const float*)d_in[6];
    const float* W2 = (const float*)d_in[7];
    const float* lg = (const float*)d_in[8];
    const float* lb = (const float*)d_in[9];
    float* out = (float*)d_out;

    static bool attr_set = false;
    if (!attr_set) {
        cudaFuncSetAttribute(gemm_mma<0>, cudaFuncAttributeMaxDynamicSharedMemorySize, GEMM_SMEM);
        cudaFuncSetAttribute(gemm_mma<1>, cudaFuncAttributeMaxDynamicSharedMemorySize, GEMM_SMEM);
        cudaFuncSetAttribute(gemm_mma<2>, cudaFuncAttributeMaxDynamicSharedMemorySize, GEMM_SMEM);
        attr_set = true;
    }

#define SYM(p, s) cudaGetSymbolAddress((void**)&p, s)
    __nv_bfloat16 *xh, *xl, *wqkvh, *wqkvl, *woh, *wol, *w1h, *w1l, *w2h, *w2l;
    __nv_bfloat16 *ctxh, *ctxl, *n1h, *n1l, *ffh, *ffl;
    float *q, *k, *v, *t1, *n1, *f2;
    SYM(xh, g_xh); SYM(xl, g_xl);
    SYM(wqkvh, g_wqkvh); SYM(wqkvl, g_wqkvl);
    SYM(woh, g_woh); SYM(wol, g_wol);
    SYM(w1h, g_w1h); SYM(w1l, g_w1l);
    SYM(w2h, g_w2h); SYM(w2l, g_w2l);
    SYM(ctxh, g_ctxh); SYM(ctxl, g_ctxl);
    SYM(n1h, g_n1h); SYM(n1l, g_n1l);
    SYM(ffh, g_ffh); SYM(ffl, g_ffl);
    SYM(q, g_q); SYM(k, g_k); SYM(v, g_v);
    SYM(t1, g_t1); SYM(n1, g_n1); SYM(f2, g_f2);
#undef SYM

    detect_mask<<<1, 256>>>(mk);
    convert_hl<<<1024, 256>>>(x,  xh, xl, NS_ * D_);
    convert_hl<<<1024, 256>>>(Wq, wqkvh,               wqkvl,               D_ * D_);
    convert_hl<<<1024, 256>>>(Wk, wqkvh + D_ * D_,     wqkvl + D_ * D_,     D_ * D_);
    convert_hl<<<1024, 256>>>(Wv, wqkvh + 2 * D_ * D_, wqkvl + 2 * D_ * D_, D_ * D_);
    convert_hl<<<1024, 256>>>(Wo, woh, wol, D_ * D_);
    convert_hl<<<1024, 256>>>(W1, w1h, w1l, DFF_ * D_);
    convert_hl<<<1024, 256>>>(W2, w2h, w2l, D_ * DFF_);

    // QKV fused: [8192, 2304] = x @ Wqkv^T, scattered into q/k/v [N,H,S,HD]
    gemm_mma<1><<<dim3(2304 / 128, NS_ / 128), 256, GEMM_SMEM>>>(
        xh, xl, wqkvh, wqkvl, q, k, v, nullptr, nullptr, NS_, 2304, D_);

    flash_attn<<<dim3(S_ / 64, H_, N_), 64>>>(q, k, v, mk, ctxh, ctxl);

    gemm_mma<0><<<dim3(D_ / 128, NS_ / 128), 256, GEMM_SMEM>>>(
        ctxh, ctxl, woh, wol, t1, nullptr, nullptr, nullptr, nullptr, NS_, D_, D_);

    ln_kernel<true><<<NS_, 256>>>(x, t1, lg, lb, n1, n1h, n1l);

    gemm_mma<2><<<dim3(DFF_ / 128, NS_ / 128), 256, GEMM_SMEM>>>(
        n1h, n1l, w1h, w1l, nullptr, nullptr, nullptr, ffh, ffl, NS_, DFF_, D_);

    gemm_mma<0><<<dim3(D_ / 128, NS_ / 128), 256, GEMM_SMEM>>>(
        ffh, ffl, w2h, w2l, f2, nullptr, nullptr, nullptr, nullptr, NS_, D_, DFF_);

    ln_kernel<false><<<NS_, 256>>>(n1, f2, lg, lb, out, nullptr, nullptr);
}

// round 5
// speedup vs baseline: 3.0687x; 1.8853x over previous
#include <cuda_runtime.h>
#include <cuda_bf16.h>
#include <math.h>
#include <stdint.h>

#define N_   4
#define S_   2048
#define D_   768
#define H_   12
#define HD_  64
#define DFF_ 3072
#define NS_  (N_ * S_)

// ======================= PTX helpers (family-agnostic, sm_80+) ==============
__device__ __forceinline__ uint32_t smem_u32(const void* p) {
    uint32_t a;
    asm("{ .reg .u64 t; cvta.to.shared.u64 t, %1; cvt.u32.u64 %0, t; }"
        : "=r"(a) : "l"(p));
    return a;
}
__device__ __forceinline__ void ldsm4(uint32_t r[4], uint32_t a) {
    asm volatile("ldmatrix.sync.aligned.m8n8.x4.shared.b16 {%0,%1,%2,%3}, [%4];"
        : "=r"(r[0]), "=r"(r[1]), "=r"(r[2]), "=r"(r[3]) : "r"(a));
}
__device__ __forceinline__ void mma16816(float c[4], const uint32_t a[4],
                                         const uint32_t b[2]) {
    asm volatile("mma.sync.aligned.m16n8k16.row.col.f32.bf16.bf16.f32 "
        "{%0,%1,%2,%3}, {%4,%5,%6,%7}, {%8,%9}, {%0,%1,%2,%3};"
        : "+f"(c[0]), "+f"(c[1]), "+f"(c[2]), "+f"(c[3])
        : "r"(a[0]), "r"(a[1]), "r"(a[2]), "r"(a[3]), "r"(b[0]), "r"(b[1]));
}
__device__ __forceinline__ void cpasync16(uint32_t dst, const void* src) {
    asm volatile("cp.async.cg.shared.global [%0], [%1], 16;" :: "r"(dst), "l"(src));
}
#define CP_COMMIT() asm volatile("cp.async.commit_group;" ::: "memory")
#define CP_WAIT(n)  asm volatile("cp.async.wait_group %0;" :: "n"(n) : "memory")

__device__ __forceinline__ void psplit(float a, float b, uint32_t& hi, uint32_t& lo) {
    const __nv_bfloat16 ha = __float2bfloat16(a), hb = __float2bfloat16(b);
    __nv_bfloat162 hv(ha, hb);
    __nv_bfloat162 lv(__float2bfloat16(a - __bfloat162float(ha)),
                      __float2bfloat16(b - __bfloat162float(hb)));
    hi = *(uint32_t*)&hv;
    lo = *(uint32_t*)&lv;
}
__device__ __forceinline__ void wsplit(__nv_bfloat16* H, __nv_bfloat16* L,
                                       size_t o, float a, float b) {
    const __nv_bfloat16 ha = __float2bfloat16(a), hb = __float2bfloat16(b);
    *(__nv_bfloat162*)(H + o) = __nv_bfloat162(ha, hb);
    *(__nv_bfloat162*)(L + o) = __nv_bfloat162(
        __float2bfloat16(a - __bfloat162float(ha)),
        __float2bfloat16(b - __bfloat162float(hb)));
}

// ======================= scratch ============================================
__device__ __nv_bfloat16 g_xh [NS_ * D_],  g_xl [NS_ * D_];
__device__ __nv_bfloat16 g_wqkvh[3 * D_ * D_], g_wqkvl[3 * D_ * D_];
__device__ __nv_bfloat16 g_woh[D_ * D_],   g_wol[D_ * D_];
__device__ __nv_bfloat16 g_w1h[DFF_ * D_], g_w1l[DFF_ * D_];
__device__ __nv_bfloat16 g_w2h[D_ * DFF_], g_w2l[D_ * DFF_];
__device__ __nv_bfloat16 g_qh [N_ * H_ * S_ * HD_], g_ql [N_ * H_ * S_ * HD_];
__device__ __nv_bfloat16 g_kh [N_ * H_ * S_ * HD_], g_kl [N_ * H_ * S_ * HD_];
__device__ float         g_vf [N_ * H_ * S_ * HD_];
__device__ __nv_bfloat16 g_vth[N_ * H_ * HD_ * S_], g_vtl[N_ * H_ * HD_ * S_];
__device__ __nv_bfloat16 g_ctxh[NS_ * D_], g_ctxl[NS_ * D_];
__device__ float g_t1 [NS_ * D_];
__device__ float g_n1 [NS_ * D_];
__device__ __nv_bfloat16 g_n1h[NS_ * D_],  g_n1l[NS_ * D_];
__device__ __nv_bfloat16 g_ffh[NS_ * DFF_], g_ffl[NS_ * DFF_];
__device__ float g_f2 [NS_ * D_];
__device__ int   g_mask64;

// ======================= mask dtype detector ================================
__global__ void detect_mask(const int* __restrict__ w)
{
    __shared__ int anynz;
    if (threadIdx.x == 0) anynz = 0;
    __syncthreads();
    int loc = 0;
    for (int i = threadIdx.x; i < 4096; i += 256)
        if (w[2 * i + 1] != 0) loc = 1;
    if (loc) atomicExch(&anynz, 1);
    __syncthreads();
    if (threadIdx.x == 0) g_mask64 = anynz ? 0 : 1;
}

// ======================= fp32 -> bf16 hi/lo split ===========================
__global__ __launch_bounds__(256) void convert_hl(const float* __restrict__ src,
                                                  __nv_bfloat16* __restrict__ h,
                                                  __nv_bfloat16* __restrict__ l,
                                                  int n)
{
    for (int i = blockIdx.x * 256 + threadIdx.x; i < n; i += gridDim.x * 256) {
        const float v = src[i];
        const __nv_bfloat16 hi = __float2bfloat16(v);
        h[i] = hi;
        l[i] = __float2bfloat16(v - __bfloat162float(hi));
    }
}

// ======================= split-bf16 HMMA GEMM ===============================
// MODE 0: plain fp32 store to C0
// MODE 1: QKV: seg0 -> Q*0.125 split (QH->Oh,QL->Ol); seg1 -> split (KH,KL); seg2 -> fp32 C0
// MODE 2: exact GELU, bf16 split store (Oh,Ol)
#define KC 32
#define TILE_B  8192
#define STAGE_B (4 * TILE_B)
#define GEMM_SMEM (2 * STAGE_B)

__device__ __forceinline__ uint32_t swz_off(int row, int c) {
    return (uint32_t)((row * 4 + (c ^ ((row >> 1) & 3))) * 16);
}

template<int MODE>
__global__ __launch_bounds__(256) void gemm_mma(
    const __nv_bfloat16* __restrict__ Ah, const __nv_bfloat16* __restrict__ Al,
    const __nv_bfloat16* __restrict__ Bh, const __nv_bfloat16* __restrict__ Bl,
    float* __restrict__ C0,
    __nv_bfloat16* __restrict__ Oh, __nv_bfloat16* __restrict__ Ol,
    __nv_bfloat16* __restrict__ KH, __nv_bfloat16* __restrict__ KL,
    int M, int Nc, int K)
{
    extern __shared__ char smem[];
    const uint32_t sb = smem_u32(smem);
    const int tid  = threadIdx.x;
    const int wid  = tid >> 5, lane = tid & 31;
    const int bm   = blockIdx.y * 128, bn = blockIdx.x * 128;
    const int wm   = (wid >> 1) * 32, wn = (wid & 1) * 64;

    const int crow = tid >> 1;
    const int cc   = (tid & 1) * 2;
    const uint32_t d0 = swz_off(crow, cc);
    const uint32_t d1 = swz_off(crow, cc + 1);
    const __nv_bfloat16* gAh = Ah + (size_t)(bm + crow) * K + cc * 8;
    const __nv_bfloat16* gAl = Al + (size_t)(bm + crow) * K + cc * 8;
    const __nv_bfloat16* gBh = Bh + (size_t)(bn + crow) * K + cc * 8;
    const __nv_bfloat16* gBl = Bl + (size_t)(bn + crow) * K + cc * 8;

    const int ra = (lane & 7) | (((lane >> 3) & 1) << 3);
    const int ca = (lane >> 4) & 1;
    const uint32_t aoff = (uint32_t)(wm * 64) + swz_off(ra, ca);
    const int rb = (lane & 7) | (((lane >> 4) & 1) << 3);
    const int cb = (lane >> 3) & 1;
    const uint32_t boff = (uint32_t)(wn * 64) + swz_off(rb, cb);

    float acc[2][8][4];
#pragma unroll
    for (int mt = 0; mt < 2; ++mt)
#pragma unroll
        for (int nt = 0; nt < 8; ++nt)
#pragma unroll
            for (int e = 0; e < 4; ++e) acc[mt][nt][e] = 0.f;

    const int NCH = K / KC;

    auto load_stage = [&](int s, int k0) {
        const uint32_t base = sb + s * STAGE_B;
        cpasync16(base + 0 * TILE_B + d0, gAh + k0);
        cpasync16(base + 0 * TILE_B + d1, gAh + k0 + 8);
        cpasync16(base + 1 * TILE_B + d0, gAl + k0);
        cpasync16(base + 1 * TILE_B + d1, gAl + k0 + 8);
        cpasync16(base + 2 * TILE_B + d0, gBh + k0);
        cpasync16(base + 2 * TILE_B + d1, gBh + k0 + 8);
        cpasync16(base + 3 * TILE_B + d0, gBl + k0);
        cpasync16(base + 3 * TILE_B + d1, gBl + k0 + 8);
    };

    load_stage(0, 0);
    CP_COMMIT();

#pragma unroll 1
    for (int ch = 0; ch < NCH; ++ch) {
        if (ch + 1 < NCH) {
            load_stage((ch + 1) & 1, (ch + 1) * KC);
            CP_COMMIT();
            CP_WAIT(1);
        } else {
            CP_WAIT(0);
        }
        __syncthreads();
        const uint32_t base = sb + (ch & 1) * STAGE_B;

#pragma unroll
        for (int ks = 0; ks < 2; ++ks) {
            const uint32_t kx = ks ? 32u : 0u;
            uint32_t a_h[2][4], a_l[2][4], bfr[4][4];
            ldsm4(a_h[0], base + 0 * TILE_B + (aoff ^ kx));
            ldsm4(a_h[1], base + 0 * TILE_B + (aoff ^ kx) + 1024);
#pragma unroll
            for (int q = 0; q < 4; ++q)
                ldsm4(bfr[q], base + 2 * TILE_B + (boff ^ kx) + q * 1024);
#pragma unroll
            for (int mt = 0; mt < 2; ++mt)
#pragma unroll
                for (int q = 0; q < 4; ++q) {
                    mma16816(acc[mt][2 * q],     a_h[mt], &bfr[q][0]);
                    mma16816(acc[mt][2 * q + 1], a_h[mt], &bfr[q][2]);
                }
            ldsm4(a_l[0], base + 1 * TILE_B + (aoff ^ kx));
            ldsm4(a_l[1], base + 1 * TILE_B + (aoff ^ kx) + 1024);
#pragma unroll
            for (int mt = 0; mt < 2; ++mt)
#pragma unroll
                for (int q = 0; q < 4; ++q) {
                    mma16816(acc[mt][2 * q],     a_l[mt], &bfr[q][0]);
                    mma16816(acc[mt][2 * q + 1], a_l[mt], &bfr[q][2]);
                }
#pragma unroll
            for (int q = 0; q < 4; ++q)
                ldsm4(bfr[q], base + 3 * TILE_B + (boff ^ kx) + q * 1024);
#pragma unroll
            for (int mt = 0; mt < 2; ++mt)
#pragma unroll
                for (int q = 0; q < 4; ++q) {
                    mma16816(acc[mt][2 * q],     a_h[mt], &bfr[q][0]);
                    mma16816(acc[mt][2 * q + 1], a_h[mt], &bfr[q][2]);
                }
        }
        __syncthreads();
    }

    const int g  = lane >> 2;
    const int tg = lane & 3;
#pragma unroll
    for (int mt = 0; mt < 2; ++mt) {
#pragma unroll
        for (int nt = 0; nt < 8; ++nt) {
            const int row = bm + wm + mt * 16 + g;
            const int col = bn + wn + nt * 8 + tg * 2;
            const float* c = acc[mt][nt];
            if (MODE == 0) {
                *(float2*)(C0 + (size_t)row * Nc + col) = make_float2(c[0], c[1]);
                *(float2*)(C0 + (size_t)(row + 8) * Nc + col) = make_float2(c[2], c[3]);
            } else if (MODE == 1) {
                const int seg = col / 768;
                const int cw  = col - seg * 768;
                const int hh  = cw >> 6, hd = cw & 63;
#pragma unroll
                for (int half = 0; half < 2; ++half) {
                    const int r = row + half * 8;
                    const int b0 = r >> 11, s0 = r & 2047;
                    float v0 = c[2 * half], v1 = c[2 * half + 1];
                    const size_t o = (((size_t)(b0 * H_ + hh) << 11) + s0) * HD_ + hd;
                    if (seg == 0) {
                        wsplit(Oh, Ol, o, v0 * 0.125f, v1 * 0.125f);
                    } else if (seg == 1) {
                        wsplit(KH, KL, o, v0, v1);
                    } else {
                        *(float2*)(C0 + o) = make_float2(v0, v1);
                    }
                }
            } else {
#pragma unroll
                for (int half = 0; half < 2; ++half) {
                    const int r = row + half * 8;
                    const float v0 = c[2 * half], v1 = c[2 * half + 1];
                    const float e0 = 0.5f * v0 * (1.f + erff(v0 * 0.70710678118654752f));
                    const float e1 = 0.5f * v1 * (1.f + erff(v1 * 0.70710678118654752f));
                    wsplit(Oh, Ol, (size_t)r * Nc + col, e0, e1);
                }
            }
        }
    }
}

// ======================= V transpose + split ================================
__global__ __launch_bounds__(256) void v_transpose(const float* __restrict__ Vf,
                                                   __nv_bfloat16* __restrict__ Vth,
                                                   __nv_bfloat16* __restrict__ Vtl)
{
    __shared__ float t[64][65];
    const int tid = threadIdx.x;
    const int s0 = blockIdx.x * 64;
    const int bh = blockIdx.y;
    const float* src = Vf + (size_t)bh * S_ * HD_ + (size_t)s0 * HD_;
#pragma unroll
    for (int e = 0; e < 16; ++e) {
        const int idx = tid + e * 256;
        t[idx >> 6][idx & 63] = src[idx];
    }
    __syncthreads();
    const size_t ob = (size_t)bh * HD_ * S_ + s0;
#pragma unroll
    for (int e = 0; e < 16; ++e) {
        const int idx = tid + e * 256;
        const int hd = idx >> 6, s = idx & 63;
        const float v = t[s][hd];
        const __nv_bfloat16 hh = __float2bfloat16(v);
        Vth[ob + (size_t)hd * S_ + s] = hh;
        Vtl[ob + (size_t)hd * S_ + s] = __float2bfloat16(v - __bfloat162float(hh));
    }
}

// ======================= HMMA flash attention ===============================
// 128 q-rows/block, 8 warps x 16 rows, 64-key tiles, double-buffered cp.async.
// smem map: [0,16384) Qh | [16384,32768) Ql | [32768,98304) 2 KV stages
//           [98304,98816) mask (2 x 256B)
#define AT_SMEM 98816
#define AT_MASK_OFF 98304

__global__ __launch_bounds__(256, 1) void attn_mma(
    const __nv_bfloat16* __restrict__ Qh, const __nv_bfloat16* __restrict__ Ql,
    const __nv_bfloat16* __restrict__ Kh, const __nv_bfloat16* __restrict__ Kl,
    const __nv_bfloat16* __restrict__ Vth, const __nv_bfloat16* __restrict__ Vtl,
    const int* __restrict__ mask,
    __nv_bfloat16* __restrict__ Oh, __nv_bfloat16* __restrict__ Ol)
{
    extern __shared__ char sm[];
    const uint32_t sb = smem_u32(sm);
    const int tid = threadIdx.x, wid = tid >> 5, lane = tid & 31;
    const int q0 = blockIdx.x * 128;
    const int h = blockIdx.y, b = blockIdx.z;
    const int bh = b * H_ + h;
    const int is64 = g_mask64;
    const uint32_t sQh = sb, sQl = sb + 16384;
    const uint32_t sStage = sb + 32768;          // + s*32768 : Kh,Kl,Vth,Vtl (8KB each)

    // ---- load Q (both splits) into smem ----
    {
        const __nv_bfloat16* srcs[2] = { Qh + (size_t)bh * S_ * HD_ + (size_t)q0 * HD_,
                                         Ql + (size_t)bh * S_ * HD_ + (size_t)q0 * HD_ };
#pragma unroll
        for (int t = 0; t < 2; ++t) {
            const uint32_t dstb = t ? sQl : sQh;
#pragma unroll
            for (int i = 0; i < 4; ++i) {
                const int u = tid + i * 256;      // 0..1023
                const int row = u >> 3, c = u & 7;
                cpasync16(dstb + row * 128 + ((c ^ (row & 7)) * 16),
                          srcs[t] + row * 64 + c * 8);
            }
        }
        CP_COMMIT();
        CP_WAIT(0);
        __syncthreads();
    }

    // ---- Q fragments (loop-invariant) ----
    const int wm = wid * 16;
    const int ra = (lane & 7) | (((lane >> 3) & 1) << 3);
    const int ca = (lane >> 4) & 1;
    uint32_t qfh[4][4], qfl[4][4];
#pragma unroll
    for (int ks = 0; ks < 4; ++ks) {
        const uint32_t off = (wm + ra) * 128 + (((2 * ks + ca) ^ (ra & 7)) * 16);
        ldsm4(qfh[ks], sQh + off);
        ldsm4(qfl[ks], sQl + off);
    }

    const int rb = (lane & 7) | (((lane >> 4) & 1) << 3);
    const int cb = (lane >> 3) & 1;
    const int g  = lane >> 2, tg = lane & 3;

    float acco[8][4];
#pragma unroll
    for (int f = 0; f < 8; ++f)
#pragma unroll
        for (int e = 0; e < 4; ++e) acco[f][e] = 0.f;
    float m0 = -1e29f, m1 = -1e29f, l0 = 0.f, l1 = 0.f;

    auto load_kv = [&](int s, int k0) {
        const uint32_t base = sStage + s * 32768;
        const __nv_bfloat16* kh = Kh + (size_t)bh * S_ * HD_ + (size_t)k0 * HD_;
        const __nv_bfloat16* kl = Kl + (size_t)bh * S_ * HD_ + (size_t)k0 * HD_;
        const __nv_bfloat16* vh = Vth + (size_t)bh * HD_ * S_ + k0;
        const __nv_bfloat16* vl = Vtl + (size_t)bh * HD_ * S_ + k0;
#pragma unroll
        for (int i = 0; i < 2; ++i) {
            const int u = tid + i * 256;   // 0..511
            const int row = u >> 3, c = u & 7;
            const uint32_t so = row * 128 + ((c ^ (row & 7)) * 16);
            cpasync16(base         + so, kh + row * 64 + c * 8);
            cpasync16(base +  8192 + so, kl + row * 64 + c * 8);
            cpasync16(base + 16384 + so, vh + (size_t)row * S_ + c * 8);
            cpasync16(base + 24576 + so, vl + (size_t)row * S_ + c * 8);
        }
        if (tid < 64) {
            const int kk = b * S_ + k0 + tid;
            const int mv = is64 ? mask[2 * kk] : mask[kk];
            ((float*)(sm + AT_MASK_OFF + s * 256))[tid] = (mv == 0) ? -1e30f : 0.f;
        }
    };

    load_kv(0, 0);
    CP_COMMIT();

#pragma unroll 1
    for (int kt = 0; kt < S_ / 64; ++kt) {
        if (kt + 1 < S_ / 64) {
            load_kv((kt + 1) & 1, (kt + 1) * 64);
            CP_COMMIT();
            CP_WAIT(1);
        } else {
            CP_WAIT(0);
        }
        __syncthreads();
        const uint32_t kbase = sStage + (kt & 1) * 32768;

        // ---- scores: 16 x 64, split 3-term ----
        float accs[8][4];
#pragma unroll
        for (int f = 0; f < 8; ++f)
#pragma unroll
            for (int e = 0; e < 4; ++e) accs[f][e] = 0.f;
#pragma unroll
        for (int ks = 0; ks < 4; ++ks) {
#pragma unroll
            for (int kg = 0; kg < 4; ++kg) {
                const uint32_t off = (kg * 16 + rb) * 128 +
                                     (((2 * ks + cb) ^ (rb & 7)) * 16);
                uint32_t bf4[4];
                ldsm4(bf4, kbase + off);
                mma16816(accs[kg * 2],     qfh[ks], &bf4[0]);
                mma16816(accs[kg * 2 + 1], qfh[ks], &bf4[2]);
                mma16816(accs[kg * 2],     qfl[ks], &bf4[0]);
                mma16816(accs[kg * 2 + 1], qfl[ks], &bf4[2]);
                ldsm4(bf4, kbase + 8192 + off);
                mma16816(accs[kg * 2],     qfh[ks], &bf4[0]);
                mma16816(accs[kg * 2 + 1], qfh[ks], &bf4[2]);
            }
        }

        // ---- mask + online softmax ----
        const float* madd = (const float*)(sm + AT_MASK_OFF + (kt & 1) * 256);
#pragma unroll
        for (int f = 0; f < 8; ++f) {
            const int keyb = (f >> 1) * 16 + (f & 1) * 8 + tg * 2;
            const float2 am = *(const float2*)&madd[keyb];
            accs[f][0] += am.x; accs[f][1] += am.y;
            accs[f][2] += am.x; accs[f][3] += am.y;
        }
        float tm0 = -1e30f, tm1 = -1e30f;
#pragma unroll
        for (int f = 0; f < 8; ++f) {
            tm0 = fmaxf(tm0, fmaxf(accs[f][0], accs[f][1]));
            tm1 = fmaxf(tm1, fmaxf(accs[f][2], accs[f][3]));
        }
        tm0 = fmaxf(tm0, __shfl_xor_sync(0xffffffffu, tm0, 1));
        tm0 = fmaxf(tm0, __shfl_xor_sync(0xffffffffu, tm0, 2));
        tm1 = fmaxf(tm1, __shfl_xor_sync(0xffffffffu, tm1, 1));
        tm1 = fmaxf(tm1, __shfl_xor_sync(0xffffffffu, tm1, 2));
        const float mn0 = fmaxf(m0, tm0), mn1 = fmaxf(m1, tm1);
        const float al0 = __expf(m0 - mn0), al1 = __expf(m1 - mn1);
        m0 = mn0; m1 = mn1;
        float ps0 = 0.f, ps1 = 0.f;
#pragma unroll
        for (int f = 0; f < 8; ++f) {
            accs[f][0] = __expf(accs[f][0] - m0); ps0 += accs[f][0];
            accs[f][1] = __expf(accs[f][1] - m0); ps0 += accs[f][1];
            accs[f][2] = __expf(accs[f][2] - m1); ps1 += accs[f][2];
            accs[f][3] = __expf(accs[f][3] - m1); ps1 += accs[f][3];
        }
        ps0 += __shfl_xor_sync(0xffffffffu, ps0, 1);
        ps0 += __shfl_xor_sync(0xffffffffu, ps0, 2);
        ps1 += __shfl_xor_sync(0xffffffffu, ps1, 1);
        ps1 += __shfl_xor_sync(0xffffffffu, ps1, 2);
        l0 = l0 * al0 + ps0;
        l1 = l1 * al1 + ps1;
#pragma unroll
        for (int f = 0; f < 8; ++f) {
            acco[f][0] *= al0; acco[f][1] *= al0;
            acco[f][2] *= al1; acco[f][3] *= al1;
        }

        // ---- P fragments (C-frag -> A-frag identity mapping) ----
        uint32_t pfh[4][4], pfl[4][4];
#pragma unroll
        for (int kg = 0; kg < 4; ++kg) {
            const int f0 = kg * 2, f1 = kg * 2 + 1;
            psplit(accs[f0][0], accs[f0][1], pfh[kg][0], pfl[kg][0]);
            psplit(accs[f0][2], accs[f0][3], pfh[kg][1], pfl[kg][1]);
            psplit(accs[f1][0], accs[f1][1], pfh[kg][2], pfl[kg][2]);
            psplit(accs[f1][2], accs[f1][3], pfh[kg][3], pfl[kg][3]);
        }

        // ---- PV: 16 x 64, split 3-term ----
#pragma unroll
        for (int kg = 0; kg < 4; ++kg) {
#pragma unroll
            for (int hg = 0; hg < 4; ++hg) {
                const uint32_t off = (hg * 16 + rb) * 128 +
                                     (((2 * kg + cb) ^ (rb & 7)) * 16);
                uint32_t bv[4];
                ldsm4(bv, kbase + 16384 + off);
                mma16816(acco[hg * 2],     pfh[kg], &bv[0]);
                mma16816(acco[hg * 2 + 1], pfh[kg], &bv[2]);
                mma16816(acco[hg * 2],     pfl[kg], &bv[0]);
                mma16816(acco[hg * 2 + 1], pfl[kg], &bv[2]);
                ldsm4(bv, kbase + 24576 + off);
                mma16816(acco[hg * 2],     pfh[kg], &bv[0]);
                mma16816(acco[hg * 2 + 1], pfh[kg], &bv[2]);
            }
        }
        __syncthreads();
    }

    // ---- epilogue: ctx split bf16 into [N,S,D] ----
    const float inv0 = 1.f / l0, inv1 = 1.f / l1;
    const int row0 = q0 + wm + g;
#pragma unroll
    for (int hg = 0; hg < 4; ++hg) {
#pragma unroll
        for (int j = 0; j < 2; ++j) {
            const int f = hg * 2 + j;
            const int col = hg * 16 + j * 8 + tg * 2;
            wsplit(Oh, Ol, (size_t)(b * S_ + row0) * D_ + h * HD_ + col,
                   acco[f][0] * inv0, acco[f][1] * inv0);
            wsplit(Oh, Ol, (size_t)(b * S_ + row0 + 8) * D_ + h * HD_ + col,
                   acco[f][2] * inv1, acco[f][3] * inv1);
        }
    }
}

// ======================= residual + LayerNorm ===============================
template<bool WB>
__global__ __launch_bounds__(256) void ln_kernel(const float* __restrict__ A,
                                                 const float* __restrict__ R,
                                                 const float* __restrict__ g,
                                                 const float* __restrict__ bta,
                                                 float* __restrict__ out,
                                                 __nv_bfloat16* __restrict__ Oh,
                                                 __nv_bfloat16* __restrict__ Ol)
{
    const int row = blockIdx.x, tid = threadIdx.x;
    const float* a = A + (size_t)row * D_;
    const float* r = R + (size_t)row * D_;
    const float v0 = a[tid]       + r[tid];
    const float v1 = a[tid + 256] + r[tid + 256];
    const float v2 = a[tid + 512] + r[tid + 512];
    float s = v0 + v1 + v2;
    float q = v0 * v0 + v1 * v1 + v2 * v2;
#pragma unroll
    for (int o = 16; o > 0; o >>= 1) {
        s += __shfl_xor_sync(0xffffffffu, s, o);
        q += __shfl_xor_sync(0xffffffffu, q, o);
    }
    __shared__ float ss[8], sq[8], stats[2];
    const int wid = tid >> 5;
    if ((tid & 31) == 0) { ss[wid] = s; sq[wid] = q; }
    __syncthreads();
    if (tid == 0) {
        float S = 0.f, Q = 0.f;
#pragma unroll
        for (int w = 0; w < 8; ++w) { S += ss[w]; Q += sq[w]; }
        const float mean = S * (1.f / 768.f);
        const float var  = Q * (1.f / 768.f) - mean * mean;
        stats[0] = mean;
        stats[1] = rsqrtf(var + 1e-5f);
    }
    __syncthreads();
    const float mean = stats[0], rstd = stats[1];
    float* o = out + (size_t)row * D_;
    const float y0 = (v0 - mean) * rstd * g[tid]       + bta[tid];
    const float y1 = (v1 - mean) * rstd * g[tid + 256] + bta[tid + 256];
    const float y2 = (v2 - mean) * rstd * g[tid + 512] + bta[tid + 512];
    o[tid] = y0; o[tid + 256] = y1; o[tid + 512] = y2;
    if (WB) {
        const size_t ob = (size_t)row * D_;
        const float ys[3] = { y0, y1, y2 };
#pragma unroll
        for (int e = 0; e < 3; ++e) {
            const __nv_bfloat16 hh = __float2bfloat16(ys[e]);
            Oh[ob + tid + 256 * e] = hh;
            Ol[ob + tid + 256 * e] =
                __float2bfloat16(ys[e] - __bfloat162float(hh));
        }
    }
}

// ======================= launch =============================================
extern "C" void kernel_launch(void* const* d_in, const int* in_sizes, int n_in,
                              void* d_out, int out_size)
{
    (void)in_sizes; (void)n_in; (void)out_size;
    const float* x  = (const float*)d_in[0];
    const int*   mk = (const int*)d_in[1];
    const float* Wq = (const float*)d_in[2];
    const float* Wk = (const float*)d_in[3];
    const float* Wv = (const float*)d_in[4];
    const float* Wo = (const float*)d_in[5];
    const float* W1 = (const float*)d_in[6];
    const float* W2 = (const float*)d_in[7];
    const float* lg = (const float*)d_in[8];
    const float* lb = (const float*)d_in[9];
    float* out = (float*)d_out;

    static bool attr_set = false;
    if (!attr_set) {
        cudaFuncSetAttribute(gemm_mma<0>, cudaFuncAttributeMaxDynamicSharedMemorySize, GEMM_SMEM);
        cudaFuncSetAttribute(gemm_mma<1>, cudaFuncAttributeMaxDynamicSharedMemorySize, GEMM_SMEM);
        cudaFuncSetAttribute(gemm_mma<2>, cudaFuncAttributeMaxDynamicSharedMemorySize, GEMM_SMEM);
        cudaFuncSetAttribute(attn_mma,    cudaFuncAttributeMaxDynamicSharedMemorySize, AT_SMEM);
        attr_set = true;
    }

#define SYM(p, s) cudaGetSymbolAddress((void**)&p, s)
    __nv_bfloat16 *xh, *xl, *wqkvh, *wqkvl, *woh, *wol, *w1h, *w1l, *w2h, *w2l;
    __nv_bfloat16 *qh, *ql, *kh, *kl, *vth, *vtl;
    __nv_bfloat16 *ctxh, *ctxl, *n1h, *n1l, *ffh, *ffl;
    float *vf, *t1, *n1, *f2;
    SYM(xh, g_xh); SYM(xl, g_xl);
    SYM(wqkvh, g_wqkvh); SYM(wqkvl, g_wqkvl);
    SYM(woh, g_woh); SYM(wol, g_wol);
    SYM(w1h, g_w1h); SYM(w1l, g_w1l);
    SYM(w2h, g_w2h); SYM(w2l, g_w2l);
    SYM(qh, g_qh); SYM(ql, g_ql); SYM(kh, g_kh); SYM(kl, g_kl);
    SYM(vf, g_vf); SYM(vth, g_vth); SYM(vtl, g_vtl);
    SYM(ctxh, g_ctxh); SYM(ctxl, g_ctxl);
    SYM(n1h, g_n1h); SYM(n1l, g_n1l);
    SYM(ffh, g_ffh); SYM(ffl, g_ffl);
    SYM(t1, g_t1); SYM(n1, g_n1); SYM(f2, g_f2);
#undef SYM

    detect_mask<<<1, 256>>>(mk);
    convert_hl<<<1024, 256>>>(x,  xh, xl, NS_ * D_);
    convert_hl<<<1024, 256>>>(Wq, wqkvh,               wqkvl,               D_ * D_);
    convert_hl<<<1024, 256>>>(Wk, wqkvh + D_ * D_,     wqkvl + D_ * D_,     D_ * D_);
    convert_hl<<<1024, 256>>>(Wv, wqkvh + 2 * D_ * D_, wqkvl + 2 * D_ * D_, D_ * D_);
    convert_hl<<<1024, 256>>>(Wo, woh, wol, D_ * D_);
    convert_hl<<<1024, 256>>>(W1, w1h, w1l, DFF_ * D_);
    convert_hl<<<1024, 256>>>(W2, w2h, w2l, D_ * DFF_);

    // QKV fused: seg0 -> Qh/Ql (scaled), seg1 -> Kh/Kl, seg2 -> Vf fp32
    gemm_mma<1><<<dim3(2304 / 128, NS_ / 128), 256, GEMM_SMEM>>>(
        xh, xl, wqkvh, wqkvl, vf, qh, ql, kh, kl, NS_, 2304, D_);

    v_transpose<<<dim3(S_ / 64, N_ * H_), 256>>>(vf, vth, vtl);

    attn_mma<<<dim3(S_ / 128, H_, N_), 256, AT_SMEM>>>(
        qh, ql, kh, kl, vth, vtl, mk, ctxh, ctxl);

    gemm_mma<0><<<dim3(D_ / 128, NS_ / 128), 256, GEMM_SMEM>>>(
        ctxh, ctxl, woh, wol, t1, nullptr, nullptr, nullptr, nullptr, NS_, D_, D_);

    ln_kernel<true><<<NS_, 256>>>(x, t1, lg, lb, n1, n1h, n1l);

    gemm_mma<2><<<dim3(DFF_ / 128, NS_ / 128), 256, GEMM_SMEM>>>(
        n1h, n1l, w1h, w1l, nullptr, ffh, ffl, nullptr, nullptr, NS_, DFF_, D_);

    gemm_mma<0><<<dim3(D_ / 128, NS_ / 128), 256, GEMM_SMEM>>>(
        ffh, ffl, w2h, w2l, f2, nullptr, nullptr, nullptr, nullptr, NS_, D_, DFF_);

    ln_kernel<false><<<NS_, 256>>>(n1, f2, lg, lb, out, nullptr, nullptr);
}

// round 6
// speedup vs baseline: 7.0532x; 2.2985x over previous
#include <cuda_runtime.h>
#include <cuda_fp16.h>
#include <math.h>
#include <stdint.h>

#define N_   4
#define S_   2048
#define D_   768
#define H_   12
#define HD_  64
#define DFF_ 3072
#define NS_  (N_ * S_)

// ======================= PTX helpers (family-agnostic, sm_80+) ==============
__device__ __forceinline__ uint32_t smem_u32(const void* p) {
    uint32_t a;
    asm("{ .reg .u64 t; cvta.to.shared.u64 t, %1; cvt.u32.u64 %0, t; }"
        : "=r"(a) : "l"(p));
    return a;
}
__device__ __forceinline__ void ldsm4(uint32_t r[4], uint32_t a) {
    asm volatile("ldmatrix.sync.aligned.m8n8.x4.shared.b16 {%0,%1,%2,%3}, [%4];"
        : "=r"(r[0]), "=r"(r[1]), "=r"(r[2]), "=r"(r[3]) : "r"(a));
}
__device__ __forceinline__ void mma16816(float c[4], const uint32_t a[4],
                                         const uint32_t b[2]) {
    asm volatile("mma.sync.aligned.m16n8k16.row.col.f32.f16.f16.f32 "
        "{%0,%1,%2,%3}, {%4,%5,%6,%7}, {%8,%9}, {%0,%1,%2,%3};"
        : "+f"(c[0]), "+f"(c[1]), "+f"(c[2]), "+f"(c[3])
        : "r"(a[0]), "r"(a[1]), "r"(a[2]), "r"(a[3]), "r"(b[0]), "r"(b[1]));
}
__device__ __forceinline__ void cpasync16(uint32_t dst, const void* src) {
    asm volatile("cp.async.cg.shared.global [%0], [%1], 16;" :: "r"(dst), "l"(src));
}
#define CP_COMMIT() asm volatile("cp.async.commit_group;" ::: "memory")
#define CP_WAIT(n)  asm volatile("cp.async.wait_group %0;" :: "n"(n) : "memory")

__device__ __forceinline__ uint32_t pack2h(float a, float b) {
    __half2 v(__float2half(a), __float2half(b));
    return *(uint32_t*)&v;
}

// ======================= scratch ============================================
__device__ __half g_x16[NS_ * D_];
__device__ __half g_wqkv[3 * D_ * D_];
__device__ __half g_wo [D_ * D_];
__device__ __half g_w1 [DFF_ * D_];
__device__ __half g_w2 [D_ * DFF_];
__device__ __half g_q16[N_ * H_ * S_ * HD_];
__device__ __half g_k16[N_ * H_ * S_ * HD_];
__device__ float  g_vf [N_ * H_ * S_ * HD_];
__device__ __half g_vt [N_ * H_ * HD_ * S_];
__device__ __half g_ctx[NS_ * D_];
__device__ float  g_t1 [NS_ * D_];
__device__ float  g_n1 [NS_ * D_];
__device__ __half g_n116[NS_ * D_];
__device__ __half g_ff [NS_ * DFF_];
__device__ float  g_f2 [NS_ * D_];
__device__ int    g_mask64;

// ======================= mask dtype detector ================================
__global__ void detect_mask(const int* __restrict__ w)
{
    __shared__ int anynz;
    if (threadIdx.x == 0) anynz = 0;
    __syncthreads();
    int loc = 0;
    for (int i = threadIdx.x; i < 4096; i += 256)
        if (w[2 * i + 1] != 0) loc = 1;
    if (loc) atomicExch(&anynz, 1);
    __syncthreads();
    if (threadIdx.x == 0) g_mask64 = anynz ? 0 : 1;
}

// ======================= fp32 -> fp16 convert ===============================
__global__ __launch_bounds__(256) void convert16(const float* __restrict__ src,
                                                 __half* __restrict__ dst, int n)
{
    for (int i = blockIdx.x * 256 + threadIdx.x; i * 4 < n; i += gridDim.x * 256) {
        const float4 v = *(const float4*)(src + i * 4);
        __half2 a(__float2half(v.x), __float2half(v.y));
        __half2 b(__float2half(v.z), __float2half(v.w));
        *(__half2*)(dst + i * 4)     = a;
        *(__half2*)(dst + i * 4 + 2) = b;
    }
}

// ======================= fp16 HMMA GEMM =====================================
// C = A[M,K] @ B[Nc,K]^T, fp32 accum.
// MODE 0: plain fp32 store to C0
// MODE 1: QKV: seg0 -> Q*0.125 fp16 (O16); seg1 -> K fp16 (K16); seg2 -> fp32 C0
// MODE 2: exact GELU -> fp16 (O16)
#define KC 32
#define TILE_B  8192           // 128 rows x 32 fp16 = 8KB... (A 8KB + B 8KB)
#define STAGE_B (2 * TILE_B)
#define GEMM_SMEM (2 * STAGE_B)

__device__ __forceinline__ uint32_t swz_off(int row, int c) {
    return (uint32_t)((row * 4 + (c ^ ((row >> 1) & 3))) * 16);
}

template<int MODE>
__global__ __launch_bounds__(256) void gemm_mma(
    const __half* __restrict__ A, const __half* __restrict__ B,
    float* __restrict__ C0,
    __half* __restrict__ O16, __half* __restrict__ K16,
    int M, int Nc, int K)
{
    extern __shared__ char smem[];
    const uint32_t sb = smem_u32(smem);
    const int tid  = threadIdx.x;
    const int wid  = tid >> 5, lane = tid & 31;
    const int bm   = blockIdx.y * 128, bn = blockIdx.x * 128;
    const int wm   = (wid >> 1) * 32, wn = (wid & 1) * 64;

    const int crow = tid >> 1;
    const int cc   = (tid & 1) * 2;
    const uint32_t d0 = swz_off(crow, cc);
    const uint32_t d1 = swz_off(crow, cc + 1);
    const __half* gA = A + (size_t)(bm + crow) * K + cc * 8;
    const __half* gB = B + (size_t)(bn + crow) * K + cc * 8;

    const int ra = (lane & 7) | (((lane >> 3) & 1) << 3);
    const int ca = (lane >> 4) & 1;
    const uint32_t aoff = (uint32_t)(wm * 64) + swz_off(ra, ca);
    const int rb = (lane & 7) | (((lane >> 4) & 1) << 3);
    const int cb = (lane >> 3) & 1;
    const uint32_t boff = (uint32_t)(wn * 64) + swz_off(rb, cb);

    float acc[2][8][4];
#pragma unroll
    for (int mt = 0; mt < 2; ++mt)
#pragma unroll
        for (int nt = 0; nt < 8; ++nt)
#pragma unroll
            for (int e = 0; e < 4; ++e) acc[mt][nt][e] = 0.f;

    const int NCH = K / KC;

    auto load_stage = [&](int s, int k0) {
        const uint32_t base = sb + s * STAGE_B;
        cpasync16(base + d0, gA + k0);
        cpasync16(base + d1, gA + k0 + 8);
        cpasync16(base + TILE_B + d0, gB + k0);
        cpasync16(base + TILE_B + d1, gB + k0 + 8);
    };

    load_stage(0, 0);
    CP_COMMIT();

#pragma unroll 1
    for (int ch = 0; ch < NCH; ++ch) {
        if (ch + 1 < NCH) {
            load_stage((ch + 1) & 1, (ch + 1) * KC);
            CP_COMMIT();
            CP_WAIT(1);
        } else {
            CP_WAIT(0);
        }
        __syncthreads();
        const uint32_t base = sb + (ch & 1) * STAGE_B;

#pragma unroll
        for (int ks = 0; ks < 2; ++ks) {
            const uint32_t kx = ks ? 32u : 0u;
            uint32_t a_f[2][4], bfr[4][4];
            ldsm4(a_f[0], base + (aoff ^ kx));
            ldsm4(a_f[1], base + (aoff ^ kx) + 1024);
#pragma unroll
            for (int q = 0; q < 4; ++q)
                ldsm4(bfr[q], base + TILE_B + (boff ^ kx) + q * 1024);
#pragma unroll
            for (int mt = 0; mt < 2; ++mt)
#pragma unroll
                for (int q = 0; q < 4; ++q) {
                    mma16816(acc[mt][2 * q],     a_f[mt], &bfr[q][0]);
                    mma16816(acc[mt][2 * q + 1], a_f[mt], &bfr[q][2]);
                }
        }
        __syncthreads();
    }

    const int g  = lane >> 2;
    const int tg = lane & 3;
#pragma unroll
    for (int mt = 0; mt < 2; ++mt) {
#pragma unroll
        for (int nt = 0; nt < 8; ++nt) {
            const int row = bm + wm + mt * 16 + g;
            const int col = bn + wn + nt * 8 + tg * 2;
            const float* c = acc[mt][nt];
            if (MODE == 0) {
                *(float2*)(C0 + (size_t)row * Nc + col) = make_float2(c[0], c[1]);
                *(float2*)(C0 + (size_t)(row + 8) * Nc + col) = make_float2(c[2], c[3]);
            } else if (MODE == 1) {
                const int seg = col / 768;
                const int cw  = col - seg * 768;
                const int hh  = cw >> 6, hd = cw & 63;
#pragma unroll
                for (int half = 0; half < 2; ++half) {
                    const int r = row + half * 8;
                    const int b0 = r >> 11, s0 = r & 2047;
                    const float v0 = c[2 * half], v1 = c[2 * half + 1];
                    const size_t o = (((size_t)(b0 * H_ + hh) << 11) + s0) * HD_ + hd;
                    if (seg == 0) {
                        *(uint32_t*)(O16 + o) = pack2h(v0 * 0.125f, v1 * 0.125f);
                    } else if (seg == 1) {
                        *(uint32_t*)(K16 + o) = pack2h(v0, v1);
                    } else {
                        *(float2*)(C0 + o) = make_float2(v0, v1);
                    }
                }
            } else {
#pragma unroll
                for (int half = 0; half < 2; ++half) {
                    const int r = row + half * 8;
                    const float v0 = c[2 * half], v1 = c[2 * half + 1];
                    const float e0 = 0.5f * v0 * (1.f + erff(v0 * 0.70710678118654752f));
                    const float e1 = 0.5f * v1 * (1.f + erff(v1 * 0.70710678118654752f));
                    *(uint32_t*)(O16 + (size_t)r * Nc + col) = pack2h(e0, e1);
                }
            }
        }
    }
}

// ======================= V transpose (fp32 -> fp16 [N,H,HD,S]) ==============
__global__ __launch_bounds__(256) void v_transpose(const float* __restrict__ Vf,
                                                   __half* __restrict__ Vt)
{
    __shared__ float t[64][65];
    const int tid = threadIdx.x;
    const int s0 = blockIdx.x * 64;
    const int bh = blockIdx.y;
    const float* src = Vf + (size_t)bh * S_ * HD_ + (size_t)s0 * HD_;
#pragma unroll
    for (int e = 0; e < 16; ++e) {
        const int idx = tid + e * 256;
        t[idx >> 6][idx & 63] = src[idx];
    }
    __syncthreads();
    const size_t ob = (size_t)bh * HD_ * S_ + s0;
#pragma unroll
    for (int e = 0; e < 16; ++e) {
        const int idx = tid + e * 256;
        const int hd = idx >> 6, s = idx & 63;
        Vt[ob + (size_t)hd * S_ + s] = __float2half(t[s][hd]);
    }
}

// ======================= fp16 HMMA flash attention ==========================
// 128 q-rows/block, 8 warps x 16 rows, 64-key tiles, double-buffered cp.async.
// smem map: [0,16384) Q | [16384,49152) 2 KV stages (K 8KB + Vt 8KB each)
//           [49152,49664) mask (2 x 256B)
#define AT_SMEM 49664
#define AT_MASK_OFF 49152

__global__ __launch_bounds__(256) void attn_mma(
    const __half* __restrict__ Q, const __half* __restrict__ K,
    const __half* __restrict__ Vt,
    const int* __restrict__ mask,
    __half* __restrict__ O16)
{
    extern __shared__ char sm[];
    const uint32_t sb = smem_u32(sm);
    const int tid = threadIdx.x, wid = tid >> 5, lane = tid & 31;
    const int q0 = blockIdx.x * 128;
    const int h = blockIdx.y, b = blockIdx.z;
    const int bh = b * H_ + h;
    const int is64 = g_mask64;
    const uint32_t sQ = sb;
    const uint32_t sStage = sb + 16384;          // + s*16384 : K, Vt (8KB each)

    // ---- load Q into smem ----
    {
        const __half* src = Q + (size_t)bh * S_ * HD_ + (size_t)q0 * HD_;
#pragma unroll
        for (int i = 0; i < 4; ++i) {
            const int u = tid + i * 256;      // 0..1023
            const int row = u >> 3, c = u & 7;
            cpasync16(sQ + row * 128 + ((c ^ (row & 7)) * 16),
                      src + row * 64 + c * 8);
        }
        CP_COMMIT();
        CP_WAIT(0);
        __syncthreads();
    }

    // ---- Q fragments (loop-invariant) ----
    const int wm = wid * 16;
    const int ra = (lane & 7) | (((lane >> 3) & 1) << 3);
    const int ca = (lane >> 4) & 1;
    uint32_t qf[4][4];
#pragma unroll
    for (int ks = 0; ks < 4; ++ks) {
        const uint32_t off = (wm + ra) * 128 + (((2 * ks + ca) ^ (ra & 7)) * 16);
        ldsm4(qf[ks], sQ + off);
    }

    const int rb = (lane & 7) | (((lane >> 4) & 1) << 3);
    const int cb = (lane >> 3) & 1;
    const int g  = lane >> 2, tg = lane & 3;

    float acco[8][4];
#pragma unroll
    for (int f = 0; f < 8; ++f)
#pragma unroll
        for (int e = 0; e < 4; ++e) acco[f][e] = 0.f;
    float m0 = -1e29f, m1 = -1e29f, l0 = 0.f, l1 = 0.f;

    auto load_kv = [&](int s, int k0) {
        const uint32_t base = sStage + s * 16384;
        const __half* kp = K  + (size_t)bh * S_ * HD_ + (size_t)k0 * HD_;
        const __half* vp = Vt + (size_t)bh * HD_ * S_ + k0;
#pragma unroll
        for (int i = 0; i < 2; ++i) {
            const int u = tid + i * 256;   // 0..511
            const int row = u >> 3, c = u & 7;
            const uint32_t so = row * 128 + ((c ^ (row & 7)) * 16);
            cpasync16(base        + so, kp + row * 64 + c * 8);
            cpasync16(base + 8192 + so, vp + (size_t)row * S_ + c * 8);
        }
        if (tid < 64) {
            const int kk = b * S_ + k0 + tid;
            const int mv = is64 ? mask[2 * kk] : mask[kk];
            ((float*)(sm + AT_MASK_OFF + s * 256))[tid] = (mv == 0) ? -1e30f : 0.f;
        }
    };

    load_kv(0, 0);
    CP_COMMIT();

#pragma unroll 1
    for (int kt = 0; kt < S_ / 64; ++kt) {
        if (kt + 1 < S_ / 64) {
            load_kv((kt + 1) & 1, (kt + 1) * 64);
            CP_COMMIT();
            CP_WAIT(1);
        } else {
            CP_WAIT(0);
        }
        __syncthreads();
        const uint32_t kbase = sStage + (kt & 1) * 16384;

        // ---- scores: 16 x 64 ----
        float accs[8][4];
#pragma unroll
        for (int f = 0; f < 8; ++f)
#pragma unroll
            for (int e = 0; e < 4; ++e) accs[f][e] = 0.f;
#pragma unroll
        for (int ks = 0; ks < 4; ++ks) {
#pragma unroll
            for (int kg = 0; kg < 4; ++kg) {
                const uint32_t off = (kg * 16 + rb) * 128 +
                                     (((2 * ks + cb) ^ (rb & 7)) * 16);
                uint32_t bf4[4];
                ldsm4(bf4, kbase + off);
                mma16816(accs[kg * 2],     qf[ks], &bf4[0]);
                mma16816(accs[kg * 2 + 1], qf[ks], &bf4[2]);
            }
        }

        // ---- mask + online softmax ----
        const float* madd = (const float*)(sm + AT_MASK_OFF + (kt & 1) * 256);
#pragma unroll
        for (int f = 0; f < 8; ++f) {
            const int keyb = (f >> 1) * 16 + (f & 1) * 8 + tg * 2;
            const float2 am = *(const float2*)&madd[keyb];
            accs[f][0] += am.x; accs[f][1] += am.y;
            accs[f][2] += am.x; accs[f][3] += am.y;
        }
        float tm0 = -1e30f, tm1 = -1e30f;
#pragma unroll
        for (int f = 0; f < 8; ++f) {
            tm0 = fmaxf(tm0, fmaxf(accs[f][0], accs[f][1]));
            tm1 = fmaxf(tm1, fmaxf(accs[f][2], accs[f][3]));
        }
        tm0 = fmaxf(tm0, __shfl_xor_sync(0xffffffffu, tm0, 1));
        tm0 = fmaxf(tm0, __shfl_xor_sync(0xffffffffu, tm0, 2));
        tm1 = fmaxf(tm1, __shfl_xor_sync(0xffffffffu, tm1, 1));
        tm1 = fmaxf(tm1, __shfl_xor_sync(0xffffffffu, tm1, 2));
        const float mn0 = fmaxf(m0, tm0), mn1 = fmaxf(m1, tm1);
        const float al0 = __expf(m0 - mn0), al1 = __expf(m1 - mn1);
        m0 = mn0; m1 = mn1;
        float ps0 = 0.f, ps1 = 0.f;
#pragma unroll
        for (int f = 0; f < 8; ++f) {
            accs[f][0] = __expf(accs[f][0] - m0); ps0 += accs[f][0];
            accs[f][1] = __expf(accs[f][1] - m0); ps0 += accs[f][1];
            accs[f][2] = __expf(accs[f][2] - m1); ps1 += accs[f][2];
            accs[f][3] = __expf(accs[f][3] - m1); ps1 += accs[f][3];
        }
        ps0 += __shfl_xor_sync(0xffffffffu, ps0, 1);
        ps0 += __shfl_xor_sync(0xffffffffu, ps0, 2);
        ps1 += __shfl_xor_sync(0xffffffffu, ps1, 1);
        ps1 += __shfl_xor_sync(0xffffffffu, ps1, 2);
        l0 = l0 * al0 + ps0;
        l1 = l1 * al1 + ps1;
#pragma unroll
        for (int f = 0; f < 8; ++f) {
            acco[f][0] *= al0; acco[f][1] *= al0;
            acco[f][2] *= al1; acco[f][3] *= al1;
        }

        // ---- P fragments (C-frag -> A-frag identity mapping) ----
        uint32_t pf[4][4];
#pragma unroll
        for (int kg = 0; kg < 4; ++kg) {
            const int f0 = kg * 2, f1 = kg * 2 + 1;
            pf[kg][0] = pack2h(accs[f0][0], accs[f0][1]);
            pf[kg][1] = pack2h(accs[f0][2], accs[f0][3]);
            pf[kg][2] = pack2h(accs[f1][0], accs[f1][1]);
            pf[kg][3] = pack2h(accs[f1][2], accs[f1][3]);
        }

        // ---- PV: 16 x 64 ----
#pragma unroll
        for (int kg = 0; kg < 4; ++kg) {
#pragma unroll
            for (int hg = 0; hg < 4; ++hg) {
                const uint32_t off = (hg * 16 + rb) * 128 +
                                     (((2 * kg + cb) ^ (rb & 7)) * 16);
                uint32_t bv[4];
                ldsm4(bv, kbase + 8192 + off);
                mma16816(acco[hg * 2],     pf[kg], &bv[0]);
                mma16816(acco[hg * 2 + 1], pf[kg], &bv[2]);
            }
        }
        __syncthreads();
    }

    // ---- epilogue: ctx fp16 into [N,S,D] ----
    const float inv0 = 1.f / l0, inv1 = 1.f / l1;
    const int row0 = q0 + wm + g;
#pragma unroll
    for (int hg = 0; hg < 4; ++hg) {
#pragma unroll
        for (int j = 0; j < 2; ++j) {
            const int f = hg * 2 + j;
            const int col = hg * 16 + j * 8 + tg * 2;
            *(uint32_t*)(O16 + (size_t)(b * S_ + row0) * D_ + h * HD_ + col) =
                pack2h(acco[f][0] * inv0, acco[f][1] * inv0);
            *(uint32_t*)(O16 + (size_t)(b * S_ + row0 + 8) * D_ + h * HD_ + col) =
                pack2h(acco[f][2] * inv1, acco[f][3] * inv1);
        }
    }
}

// ======================= residual + LayerNorm ===============================
template<bool WB>
__global__ __launch_bounds__(256) void ln_kernel(const float* __restrict__ A,
                                                 const float* __restrict__ R,
                                                 const float* __restrict__ g,
                                                 const float* __restrict__ bta,
                                                 float* __restrict__ out,
                                                 __half* __restrict__ O16)
{
    const int row = blockIdx.x, tid = threadIdx.x;
    const float* a = A + (size_t)row * D_;
    const float* r = R + (size_t)row * D_;
    const float v0 = a[tid]       + r[tid];
    const float v1 = a[tid + 256] + r[tid + 256];
    const float v2 = a[tid + 512] + r[tid + 512];
    float s = v0 + v1 + v2;
    float q = v0 * v0 + v1 * v1 + v2 * v2;
#pragma unroll
    for (int o = 16; o > 0; o >>= 1) {
        s += __shfl_xor_sync(0xffffffffu, s, o);
        q += __shfl_xor_sync(0xffffffffu, q, o);
    }
    __shared__ float ss[8], sq[8], stats[2];
    const int wid = tid >> 5;
    if ((tid & 31) == 0) { ss[wid] = s; sq[wid] = q; }
    __syncthreads();
    if (tid == 0) {
        float S = 0.f, Q = 0.f;
#pragma unroll
        for (int w = 0; w < 8; ++w) { S += ss[w]; Q += sq[w]; }
        const float mean = S * (1.f / 768.f);
        const float var  = Q * (1.f / 768.f) - mean * mean;
        stats[0] = mean;
        stats[1] = rsqrtf(var + 1e-5f);
    }
    __syncthreads();
    const float mean = stats[0], rstd = stats[1];
    float* o = out + (size_t)row * D_;
    const float y0 = (v0 - mean) * rstd * g[tid]       + bta[tid];
    const float y1 = (v1 - mean) * rstd * g[tid + 256] + bta[tid + 256];
    const float y2 = (v2 - mean) * rstd * g[tid + 512] + bta[tid + 512];
    o[tid] = y0; o[tid + 256] = y1; o[tid + 512] = y2;
    if (WB) {
        const size_t ob = (size_t)row * D_;
        O16[ob + tid]       = __float2half(y0);
        O16[ob + tid + 256] = __float2half(y1);
        O16[ob + tid + 512] = __float2half(y2);
    }
}

// ======================= launch =============================================
extern "C" void kernel_launch(void* const* d_in, const int* in_sizes, int n_in,
                              void* d_out, int out_size)
{
    (void)in_sizes; (void)n_in; (void)out_size;
    const float* x  = (const float*)d_in[0];
    const int*   mk = (const int*)d_in[1];
    const float* Wq = (const float*)d_in[2];
    const float* Wk = (const float*)d_in[3];
    const float* Wv = (const float*)d_in[4];
    const float* Wo = (const float*)d_in[5];
    const float* W1 = (const float*)d_in[6];
    const float* W2 = (const float*)d_in[7];
    const float* lg = (const float*)d_in[8];
    const float* lb = (const float*)d_in[9];
    float* out = (float*)d_out;

    static bool attr_set = false;
    if (!attr_set) {
        cudaFuncSetAttribute(gemm_mma<0>, cudaFuncAttributeMaxDynamicSharedMemorySize, GEMM_SMEM);
        cudaFuncSetAttribute(gemm_mma<1>, cudaFuncAttributeMaxDynamicSharedMemorySize, GEMM_SMEM);
        cudaFuncSetAttribute(gemm_mma<2>, cudaFuncAttributeMaxDynamicSharedMemorySize, GEMM_SMEM);
        cudaFuncSetAttribute(attn_mma,    cudaFuncAttributeMaxDynamicSharedMemorySize, AT_SMEM);
        attr_set = true;
    }

#define SYM(p, s) cudaGetSymbolAddress((void**)&p, s)
    __half *x16, *wqkv, *wo, *w1, *w2, *q16, *k16, *vt, *ctx, *n116, *ff;
    float *vf, *t1, *n1, *f2;
    SYM(x16, g_x16); SYM(wqkv, g_wqkv); SYM(wo, g_wo);
    SYM(w1, g_w1); SYM(w2, g_w2);
    SYM(q16, g_q16); SYM(k16, g_k16);
    SYM(vf, g_vf); SYM(vt, g_vt);
    SYM(ctx, g_ctx); SYM(n116, g_n116); SYM(ff, g_ff);
    SYM(t1, g_t1); SYM(n1, g_n1); SYM(f2, g_f2);
#undef SYM

    detect_mask<<<1, 256>>>(mk);
    convert16<<<512, 256>>>(x,  x16, NS_ * D_);
    convert16<<<512, 256>>>(Wq, wqkv,               D_ * D_);
    convert16<<<512, 256>>>(Wk, wqkv + D_ * D_,     D_ * D_);
    convert16<<<512, 256>>>(Wv, wqkv + 2 * D_ * D_, D_ * D_);
    convert16<<<512, 256>>>(Wo, wo, D_ * D_);
    convert16<<<512, 256>>>(W1, w1, DFF_ * D_);
    convert16<<<512, 256>>>(W2, w2, D_ * DFF_);

    // QKV fused: seg0 -> Q (scaled) fp16, seg1 -> K fp16, seg2 -> V fp32
    gemm_mma<1><<<dim3(2304 / 128, NS_ / 128), 256, GEMM_SMEM>>>(
        x16, wqkv, vf, q16, k16, NS_, 2304, D_);

    v_transpose<<<dim3(S_ / 64, N_ * H_), 256>>>(vf, vt);

    attn_mma<<<dim3(S_ / 128, H_, N_), 256, AT_SMEM>>>(q16, k16, vt, mk, ctx);

    gemm_mma<0><<<dim3(D_ / 128, NS_ / 128), 256, GEMM_SMEM>>>(
        ctx, wo, t1, nullptr, nullptr, NS_, D_, D_);

    ln_kernel<true><<<NS_, 256>>>(x, t1, lg, lb, n1, n116);

    gemm_mma<2><<<dim3(DFF_ / 128, NS_ / 128), 256, GEMM_SMEM>>>(
        n116, w1, nullptr, ff, nullptr, NS_, DFF_, D_);

    gemm_mma<0><<<dim3(D_ / 128, NS_ / 128), 256, GEMM_SMEM>>>(
        ff, w2, f2, nullptr, nullptr, NS_, D_, DFF_);

    ln_kernel<false><<<NS_, 256>>>(n1, f2, lg, lb, out, nullptr);
}

// round 7
// speedup vs baseline: 8.1349x; 1.1534x over previous
#include <cuda_runtime.h>
#include <cuda_fp16.h>
#include <math.h>
#include <stdint.h>

#define N_   4
#define S_   2048
#define D_   768
#define H_   12
#define HD_  64
#define DFF_ 3072
#define NS_  (N_ * S_)

// ======================= PTX helpers (family-agnostic, sm_80+) ==============
__device__ __forceinline__ uint32_t smem_u32(const void* p) {
    uint32_t a;
    asm("{ .reg .u64 t; cvta.to.shared.u64 t, %1; cvt.u32.u64 %0, t; }"
        : "=r"(a) : "l"(p));
    return a;
}
__device__ __forceinline__ void ldsm4(uint32_t r[4], uint32_t a) {
    asm volatile("ldmatrix.sync.aligned.m8n8.x4.shared.b16 {%0,%1,%2,%3}, [%4];"
        : "=r"(r[0]), "=r"(r[1]), "=r"(r[2]), "=r"(r[3]) : "r"(a));
}
__device__ __forceinline__ void mma16816(float c[4], const uint32_t a[4],
                                         const uint32_t b[2]) {
    asm volatile("mma.sync.aligned.m16n8k16.row.col.f32.f16.f16.f32 "
        "{%0,%1,%2,%3}, {%4,%5,%6,%7}, {%8,%9}, {%0,%1,%2,%3};"
        : "+f"(c[0]), "+f"(c[1]), "+f"(c[2]), "+f"(c[3])
        : "r"(a[0]), "r"(a[1]), "r"(a[2]), "r"(a[3]), "r"(b[0]), "r"(b[1]));
}
__device__ __forceinline__ void cpasync16(uint32_t dst, const void* src) {
    asm volatile("cp.async.cg.shared.global [%0], [%1], 16;" :: "r"(dst), "l"(src));
}
#define CP_COMMIT() asm volatile("cp.async.commit_group;" ::: "memory")
#define CP_WAIT(n)  asm volatile("cp.async.wait_group %0;" :: "n"(n) : "memory")

__device__ __forceinline__ uint32_t pack2h(float a, float b) {
    __half2 v(__float2half(a), __float2half(b));
    return *(uint32_t*)&v;
}

// ======================= scratch ============================================
__device__ __half g_x16[NS_ * D_];
__device__ __half g_wqkv[3 * D_ * D_];
__device__ __half g_wo [D_ * D_];
__device__ __half g_w1 [DFF_ * D_];
__device__ __half g_w2 [D_ * DFF_];
__device__ __half g_q16[N_ * H_ * S_ * HD_];
__device__ __half g_k16[N_ * H_ * S_ * HD_];
__device__ __half g_v16[N_ * H_ * S_ * HD_];
__device__ __half g_vt [N_ * H_ * HD_ * S_];
__device__ __half g_ctx[NS_ * D_];
__device__ float  g_t1 [NS_ * D_];
__device__ float  g_n1 [NS_ * D_];
__device__ __half g_n116[NS_ * D_];
__device__ __half g_ff [NS_ * DFF_];
__device__ float  g_f2 [NS_ * D_];
__device__ int    g_mask64;

// ======================= mask dtype detector ================================
__global__ void detect_mask(const int* __restrict__ w)
{
    __shared__ int anynz;
    if (threadIdx.x == 0) anynz = 0;
    __syncthreads();
    int loc = 0;
    for (int i = threadIdx.x; i < 4096; i += 256)
        if (w[2 * i + 1] != 0) loc = 1;
    if (loc) atomicExch(&anynz, 1);
    __syncthreads();
    if (threadIdx.x == 0) g_mask64 = anynz ? 0 : 1;
}

// ======================= fp32 -> fp16 converts ==============================
__global__ __launch_bounds__(256) void convert16(const float* __restrict__ src,
                                                 __half* __restrict__ dst, int n)
{
    for (int i = blockIdx.x * 256 + threadIdx.x; i * 4 < n; i += gridDim.x * 256) {
        const float4 v = *(const float4*)(src + i * 4);
        *(__half2*)(dst + i * 4)     = __half2(__float2half(v.x), __float2half(v.y));
        *(__half2*)(dst + i * 4 + 2) = __half2(__float2half(v.z), __float2half(v.w));
    }
}

// all 6 weight tensors in one launch (vec4 units)
#define DDV (147456)            // D*D/4
#define W1V (589824)            // DFF*D/4
__global__ __launch_bounds__(256) void convert_w(
    const float* __restrict__ Wq, const float* __restrict__ Wk,
    const float* __restrict__ Wv, const float* __restrict__ Wo,
    const float* __restrict__ W1, const float* __restrict__ W2,
    __half* __restrict__ wqkv, __half* __restrict__ wo,
    __half* __restrict__ w1,   __half* __restrict__ w2)
{
    const int total = 3 * DDV + DDV + 2 * W1V;   // 1769472
    for (int i = blockIdx.x * 256 + threadIdx.x; i < total; i += gridDim.x * 256) {
        const float* s; __half* d; int j;
        if (i < 3 * DDV) {
            const int seg = i / DDV;
            j = i - seg * DDV;
            s = (seg == 0) ? Wq : (seg == 1) ? Wk : Wv;
            d = wqkv + (size_t)seg * (D_ * D_);
        } else if (i < 4 * DDV) {
            j = i - 3 * DDV; s = Wo; d = wo;
        } else if (i < 4 * DDV + W1V) {
            j = i - 4 * DDV; s = W1; d = w1;
        } else {
            j = i - 4 * DDV - W1V; s = W2; d = w2;
        }
        const float4 v = *(const float4*)(s + (size_t)j * 4);
        *(__half2*)(d + (size_t)j * 4)     = __half2(__float2half(v.x), __float2half(v.y));
        *(__half2*)(d + (size_t)j * 4 + 2) = __half2(__float2half(v.z), __float2half(v.w));
    }
}

// ======================= fp16 HMMA GEMM (KC=64, 3-stage) ====================
// C = A[M,K] @ B[Nc,K]^T, fp32 accum.
// MODE 0: plain fp32 store to C0
// MODE 1: QKV: seg0 -> Q*0.125 fp16 (O16); seg1 -> K fp16 (K16); seg2 -> V fp16 (V16)
// MODE 2: exact GELU -> fp16 (O16)
#define KC 64
#define TILE_B  16384          // 128 rows x 64 fp16 (128B/row)
#define STAGE_B (2 * TILE_B)
#define NSTG 3
#define GEMM_SMEM (NSTG * STAGE_B)   // 96 KB

template<int MODE>
__global__ __launch_bounds__(256) void gemm_mma(
    const __half* __restrict__ A, const __half* __restrict__ B,
    float* __restrict__ C0,
    __half* __restrict__ O16, __half* __restrict__ K16, __half* __restrict__ V16,
    int M, int Nc, int K)
{
    extern __shared__ char smem[];
    const uint32_t sb = smem_u32(smem);
    const int tid  = threadIdx.x;
    const int wid  = tid >> 5, lane = tid & 31;
    const int bm   = blockIdx.y * 128, bn = blockIdx.x * 128;
    const int wm   = (wid >> 1) * 32, wn = (wid & 1) * 64;

    // ---- cp.async mapping: 128 rows x 128B per tile; 4 x 16B per thread ----
    const int r0 = tid >> 3, c0 = tid & 7;
    const uint32_t doff = (uint32_t)(r0 * 128 + ((c0 ^ (r0 & 7)) * 16));
    const __half* gA = A + (size_t)(bm + r0) * K + c0 * 8;
    const __half* gB = B + (size_t)(bn + r0) * K + c0 * 8;

    // ---- ldmatrix per-lane offsets ----
    const int ra = (lane & 7) | (((lane >> 3) & 1) << 3);
    const int ca = (lane >> 4) & 1;
    const int rb = (lane & 7) | (((lane >> 4) & 1) << 3);
    const int cb = (lane >> 3) & 1;
    const uint32_t aRow = (uint32_t)((wm + ra) * 128);
    const uint32_t bRow = (uint32_t)((wn + rb) * 128);
    const int aswz = ra & 7, bswz = rb & 7;

    float acc[2][8][4];
#pragma unroll
    for (int mt = 0; mt < 2; ++mt)
#pragma unroll
        for (int nt = 0; nt < 8; ++nt)
#pragma unroll
            for (int e = 0; e < 4; ++e) acc[mt][nt][e] = 0.f;

    const int NCH = K / KC;

    auto load_stage = [&](int slot, int k0) {
        const uint32_t base = sb + slot * STAGE_B;
#pragma unroll
        for (int i = 0; i < 4; ++i) {
            cpasync16(base + doff + i * 4096,          gA + k0 + (size_t)i * 32 * K);
            cpasync16(base + TILE_B + doff + i * 4096, gB + k0 + (size_t)i * 32 * K);
        }
    };

    load_stage(0, 0);
    CP_COMMIT();
    load_stage(1, KC);
    CP_COMMIT();

    int slot = 0;
#pragma unroll 1
    for (int ch = 0; ch < NCH; ++ch) {
        if (ch < NCH - 1) { CP_WAIT(1); } else { CP_WAIT(0); }
        __syncthreads();
        if (ch + 2 < NCH) {
            int ns = slot + 2; if (ns >= NSTG) ns -= NSTG;
            load_stage(ns, (ch + 2) * KC);
            CP_COMMIT();
        }
        const uint32_t base = sb + slot * STAGE_B;

#pragma unroll
        for (int ks = 0; ks < 4; ++ks) {
            const uint32_t axo = aRow + (((2 * ks + ca) ^ aswz) * 16);
            const uint32_t bxo = bRow + (((2 * ks + cb) ^ bswz) * 16);
            uint32_t a_f[2][4], bfr[4][4];
            ldsm4(a_f[0], base + axo);
            ldsm4(a_f[1], base + axo + 2048);
#pragma unroll
            for (int q = 0; q < 4; ++q)
                ldsm4(bfr[q], base + TILE_B + bxo + q * 2048);
#pragma unroll
            for (int mt = 0; mt < 2; ++mt)
#pragma unroll
                for (int q = 0; q < 4; ++q) {
                    mma16816(acc[mt][2 * q],     a_f[mt], &bfr[q][0]);
                    mma16816(acc[mt][2 * q + 1], a_f[mt], &bfr[q][2]);
                }
        }
        if (++slot >= NSTG) slot = 0;
    }

    const int g  = lane >> 2;
    const int tg = lane & 3;
#pragma unroll
    for (int mt = 0; mt < 2; ++mt) {
#pragma unroll
        for (int nt = 0; nt < 8; ++nt) {
            const int row = bm + wm + mt * 16 + g;
            const int col = bn + wn + nt * 8 + tg * 2;
            const float* c = acc[mt][nt];
            if (MODE == 0) {
                *(float2*)(C0 + (size_t)row * Nc + col) = make_float2(c[0], c[1]);
                *(float2*)(C0 + (size_t)(row + 8) * Nc + col) = make_float2(c[2], c[3]);
            } else if (MODE == 1) {
                const int seg = col / 768;
                const int cw  = col - seg * 768;
                const int hh  = cw >> 6, hd = cw & 63;
#pragma unroll
                for (int half = 0; half < 2; ++half) {
                    const int r = row + half * 8;
                    const int b0 = r >> 11, s0 = r & 2047;
                    const float v0 = c[2 * half], v1 = c[2 * half + 1];
                    const size_t o = (((size_t)(b0 * H_ + hh) << 11) + s0) * HD_ + hd;
                    if (seg == 0) {
                        *(uint32_t*)(O16 + o) = pack2h(v0 * 0.125f, v1 * 0.125f);
                    } else if (seg == 1) {
                        *(uint32_t*)(K16 + o) = pack2h(v0, v1);
                    } else {
                        *(uint32_t*)(V16 + o) = pack2h(v0, v1);
                    }
                }
            } else {
#pragma unroll
                for (int half = 0; half < 2; ++half) {
                    const int r = row + half * 8;
                    const float v0 = c[2 * half], v1 = c[2 * half + 1];
                    const float e0 = 0.5f * v0 * (1.f + erff(v0 * 0.70710678118654752f));
                    const float e1 = 0.5f * v1 * (1.f + erff(v1 * 0.70710678118654752f));
                    *(uint32_t*)(O16 + (size_t)r * Nc + col) = pack2h(e0, e1);
                }
            }
        }
    }
}

// ======================= V transpose (fp16 -> fp16 [N,H,HD,S]) ==============
__global__ __launch_bounds__(256) void v_transpose(const __half* __restrict__ V,
                                                   __half* __restrict__ Vt)
{
    __shared__ __half t[64][66];
    const int tid = threadIdx.x;
    const int s0 = blockIdx.x * 64;
    const int bh = blockIdx.y;
    const __half* src = V + (size_t)bh * S_ * HD_ + (size_t)s0 * HD_;
#pragma unroll
    for (int e = 0; e < 16; ++e) {
        const int idx = tid + e * 256;
        t[idx >> 6][idx & 63] = src[idx];
    }
    __syncthreads();
    const size_t ob = (size_t)bh * HD_ * S_ + s0;
#pragma unroll
    for (int e = 0; e < 16; ++e) {
        const int idx = tid + e * 256;
        const int hd = idx >> 6, s = idx & 63;
        Vt[ob + (size_t)hd * S_ + s] = t[s][hd];
    }
}

// ======================= fp16 HMMA flash attention ==========================
// 128 q-rows/block, 8 warps x 16 rows, 64-key tiles, double-buffered cp.async.
// smem map: [0,16384) Q | [16384,49152) 2 KV stages (K 8KB + Vt 8KB each)
//           [49152,49664) mask (2 x 256B)
#define AT_SMEM 49664
#define AT_MASK_OFF 49152

__global__ __launch_bounds__(256) void attn_mma(
    const __half* __restrict__ Q, const __half* __restrict__ K,
    const __half* __restrict__ Vt,
    const int* __restrict__ mask,
    __half* __restrict__ O16)
{
    extern __shared__ char sm[];
    const uint32_t sb = smem_u32(sm);
    const int tid = threadIdx.x, wid = tid >> 5, lane = tid & 31;
    const int q0 = blockIdx.x * 128;
    const int h = blockIdx.y, b = blockIdx.z;
    const int bh = b * H_ + h;
    const int is64 = g_mask64;
    const uint32_t sQ = sb;
    const uint32_t sStage = sb + 16384;          // + s*16384 : K, Vt (8KB each)

    // ---- load Q into smem ----
    {
        const __half* src = Q + (size_t)bh * S_ * HD_ + (size_t)q0 * HD_;
#pragma unroll
        for (int i = 0; i < 4; ++i) {
            const int u = tid + i * 256;      // 0..1023
            const int row = u >> 3, c = u & 7;
            cpasync16(sQ + row * 128 + ((c ^ (row & 7)) * 16),
                      src + row * 64 + c * 8);
        }
        CP_COMMIT();
        CP_WAIT(0);
        __syncthreads();
    }

    // ---- Q fragments (loop-invariant) ----
    const int wm = wid * 16;
    const int ra = (lane & 7) | (((lane >> 3) & 1) << 3);
    const int ca = (lane >> 4) & 1;
    uint32_t qf[4][4];
#pragma unroll
    for (int ks = 0; ks < 4; ++ks) {
        const uint32_t off = (wm + ra) * 128 + (((2 * ks + ca) ^ (ra & 7)) * 16);
        ldsm4(qf[ks], sQ + off);
    }

    const int rb = (lane & 7) | (((lane >> 4) & 1) << 3);
    const int cb = (lane >> 3) & 1;
    const int g  = lane >> 2, tg = lane & 3;

    float acco[8][4];
#pragma unroll
    for (int f = 0; f < 8; ++f)
#pragma unroll
        for (int e = 0; e < 4; ++e) acco[f][e] = 0.f;
    float m0 = -1e29f, m1 = -1e29f, l0 = 0.f, l1 = 0.f;

    auto load_kv = [&](int s, int k0) {
        const uint32_t base = sStage + s * 16384;
        const __half* kp = K  + (size_t)bh * S_ * HD_ + (size_t)k0 * HD_;
        const __half* vp = Vt + (size_t)bh * HD_ * S_ + k0;
#pragma unroll
        for (int i = 0; i < 2; ++i) {
            const int u = tid + i * 256;   // 0..511
            const int row = u >> 3, c = u & 7;
            const uint32_t so = row * 128 + ((c ^ (row & 7)) * 16);
            cpasync16(base        + so, kp + row * 64 + c * 8);
            cpasync16(base + 8192 + so, vp + (size_t)row * S_ + c * 8);
        }
        if (tid < 64) {
            const int kk = b * S_ + k0 + tid;
            const int mv = is64 ? mask[2 * kk] : mask[kk];
            ((float*)(sm + AT_MASK_OFF + s * 256))[tid] = (mv == 0) ? -1e30f : 0.f;
        }
    };

    load_kv(0, 0);
    CP_COMMIT();

#pragma unroll 1
    for (int kt = 0; kt < S_ / 64; ++kt) {
        if (kt + 1 < S_ / 64) {
            load_kv((kt + 1) & 1, (kt + 1) * 64);
            CP_COMMIT();
            CP_WAIT(1);
        } else {
            CP_WAIT(0);
        }
        __syncthreads();
        const uint32_t kbase = sStage + (kt & 1) * 16384;

        // ---- scores: 16 x 64 ----
        float accs[8][4];
#pragma unroll
        for (int f = 0; f < 8; ++f)
#pragma unroll
            for (int e = 0; e < 4; ++e) accs[f][e] = 0.f;
#pragma unroll
        for (int ks = 0; ks < 4; ++ks) {
#pragma unroll
            for (int kg = 0; kg < 4; ++kg) {
                const uint32_t off = (kg * 16 + rb) * 128 +
                                     (((2 * ks + cb) ^ (rb & 7)) * 16);
                uint32_t bf4[4];
                ldsm4(bf4, kbase + off);
                mma16816(accs[kg * 2],     qf[ks], &bf4[0]);
                mma16816(accs[kg * 2 + 1], qf[ks], &bf4[2]);
            }
        }

        // ---- mask + online softmax ----
        const float* madd = (const float*)(sm + AT_MASK_OFF + (kt & 1) * 256);
#pragma unroll
        for (int f = 0; f < 8; ++f) {
            const int keyb = (f >> 1) * 16 + (f & 1) * 8 + tg * 2;
            const float2 am = *(const float2*)&madd[keyb];
            accs[f][0] += am.x; accs[f][1] += am.y;
            accs[f][2] += am.x; accs[f][3] += am.y;
        }
        float tm0 = -1e30f, tm1 = -1e30f;
#pragma unroll
        for (int f = 0; f < 8; ++f) {
            tm0 = fmaxf(tm0, fmaxf(accs[f][0], accs[f][1]));
            tm1 = fmaxf(tm1, fmaxf(accs[f][2], accs[f][3]));
        }
        tm0 = fmaxf(tm0, __shfl_xor_sync(0xffffffffu, tm0, 1));
        tm0 = fmaxf(tm0, __shfl_xor_sync(0xffffffffu, tm0, 2));
        tm1 = fmaxf(tm1, __shfl_xor_sync(0xffffffffu, tm1, 1));
        tm1 = fmaxf(tm1, __shfl_xor_sync(0xffffffffu, tm1, 2));
        const float mn0 = fmaxf(m0, tm0), mn1 = fmaxf(m1, tm1);
        const float al0 = __expf(m0 - mn0), al1 = __expf(m1 - mn1);
        m0 = mn0; m1 = mn1;
        float ps0 = 0.f, ps1 = 0.f;
#pragma unroll
        for (int f = 0; f < 8; ++f) {
            accs[f][0] = __expf(accs[f][0] - m0); ps0 += accs[f][0];
            accs[f][1] = __expf(accs[f][1] - m0); ps0 += accs[f][1];
            accs[f][2] = __expf(accs[f][2] - m1); ps1 += accs[f][2];
            accs[f][3] = __expf(accs[f][3] - m1); ps1 += accs[f][3];
        }
        ps0 += __shfl_xor_sync(0xffffffffu, ps0, 1);
        ps0 += __shfl_xor_sync(0xffffffffu, ps0, 2);
        ps1 += __shfl_xor_sync(0xffffffffu, ps1, 1);
        ps1 += __shfl_xor_sync(0xffffffffu, ps1, 2);
        l0 = l0 * al0 + ps0;
        l1 = l1 * al1 + ps1;
#pragma unroll
        for (int f = 0; f < 8; ++f) {
            acco[f][0] *= al0; acco[f][1] *= al0;
            acco[f][2] *= al1; acco[f][3] *= al1;
        }

        // ---- P fragments (C-frag -> A-frag identity mapping) ----
        uint32_t pf[4][4];
#pragma unroll
        for (int kg = 0; kg < 4; ++kg) {
            const int f0 = kg * 2, f1 = kg * 2 + 1;
            pf[kg][0] = pack2h(accs[f0][0], accs[f0][1]);
            pf[kg][1] = pack2h(accs[f0][2], accs[f0][3]);
            pf[kg][2] = pack2h(accs[f1][0], accs[f1][1]);
            pf[kg][3] = pack2h(accs[f1][2], accs[f1][3]);
        }

        // ---- PV: 16 x 64 ----
#pragma unroll
        for (int kg = 0; kg < 4; ++kg) {
#pragma unroll
            for (int hg = 0; hg < 4; ++hg) {
                const uint32_t off = (hg * 16 + rb) * 128 +
                                     (((2 * kg + cb) ^ (rb & 7)) * 16);
                uint32_t bv[4];
                ldsm4(bv, kbase + 8192 + off);
                mma16816(acco[hg * 2],     pf[kg], &bv[0]);
                mma16816(acco[hg * 2 + 1], pf[kg], &bv[2]);
            }
        }
        __syncthreads();
    }

    // ---- epilogue: ctx fp16 into [N,S,D] ----
    const float inv0 = 1.f / l0, inv1 = 1.f / l1;
    const int row0 = q0 + wm + g;
#pragma unroll
    for (int hg = 0; hg < 4; ++hg) {
#pragma unroll
        for (int j = 0; j < 2; ++j) {
            const int f = hg * 2 + j;
            const int col = hg * 16 + j * 8 + tg * 2;
            *(uint32_t*)(O16 + (size_t)(b * S_ + row0) * D_ + h * HD_ + col) =
                pack2h(acco[f][0] * inv0, acco[f][1] * inv0);
            *(uint32_t*)(O16 + (size_t)(b * S_ + row0 + 8) * D_ + h * HD_ + col) =
                pack2h(acco[f][2] * inv1, acco[f][3] * inv1);
        }
    }
}

// ======================= residual + LayerNorm ===============================
template<bool WB>
__global__ __launch_bounds__(256) void ln_kernel(const float* __restrict__ A,
                                                 const float* __restrict__ R,
                                                 const float* __restrict__ g,
                                                 const float* __restrict__ bta,
                                                 float* __restrict__ out,
                                                 __half* __restrict__ O16)
{
    const int row = blockIdx.x, tid = threadIdx.x;
    const float* a = A + (size_t)row * D_;
    const float* r = R + (size_t)row * D_;
    const float v0 = a[tid]       + r[tid];
    const float v1 = a[tid + 256] + r[tid + 256];
    const float v2 = a[tid + 512] + r[tid + 512];
    float s = v0 + v1 + v2;
    float q = v0 * v0 + v1 * v1 + v2 * v2;
#pragma unroll
    for (int o = 16; o > 0; o >>= 1) {
        s += __shfl_xor_sync(0xffffffffu, s, o);
        q += __shfl_xor_sync(0xffffffffu, q, o);
    }
    __shared__ float ss[8], sq[8], stats[2];
    const int wid = tid >> 5;
    if ((tid & 31) == 0) { ss[wid] = s; sq[wid] = q; }
    __syncthreads();
    if (tid == 0) {
        float S = 0.f, Q = 0.f;
#pragma unroll
        for (int w = 0; w < 8; ++w) { S += ss[w]; Q += sq[w]; }
        const float mean = S * (1.f / 768.f);
        const float var  = Q * (1.f / 768.f) - mean * mean;
        stats[0] = mean;
        stats[1] = rsqrtf(var + 1e-5f);
    }
    __syncthreads();
    const float mean = stats[0], rstd = stats[1];
    float* o = out + (size_t)row * D_;
    const float y0 = (v0 - mean) * rstd * g[tid]       + bta[tid];
    const float y1 = (v1 - mean) * rstd * g[tid + 256] + bta[tid + 256];
    const float y2 = (v2 - mean) * rstd * g[tid + 512] + bta[tid + 512];
    o[tid] = y0; o[tid + 256] = y1; o[tid + 512] = y2;
    if (WB) {
        const size_t ob = (size_t)row * D_;
        O16[ob + tid]       = __float2half(y0);
        O16[ob + tid + 256] = __float2half(y1);
        O16[ob + tid + 512] = __float2half(y2);
    }
}

// ======================= launch =============================================
extern "C" void kernel_launch(void* const* d_in, const int* in_sizes, int n_in,
                              void* d_out, int out_size)
{
    (void)in_sizes; (void)n_in; (void)out_size;
    const float* x  = (const float*)d_in[0];
    const int*   mk = (const int*)d_in[1];
    const float* Wq = (const float*)d_in[2];
    const float* Wk = (const float*)d_in[3];
    const float* Wv = (const float*)d_in[4];
    const float* Wo = (const float*)d_in[5];
    const float* W1 = (const float*)d_in[6];
    const float* W2 = (const float*)d_in[7];
    const float* lg = (const float*)d_in[8];
    const float* lb = (const float*)d_in[9];
    float* out = (float*)d_out;

    static bool attr_set = false;
    if (!attr_set) {
        cudaFuncSetAttribute(gemm_mma<0>, cudaFuncAttributeMaxDynamicSharedMemorySize, GEMM_SMEM);
        cudaFuncSetAttribute(gemm_mma<1>, cudaFuncAttributeMaxDynamicSharedMemorySize, GEMM_SMEM);
        cudaFuncSetAttribute(gemm_mma<2>, cudaFuncAttributeMaxDynamicSharedMemorySize, GEMM_SMEM);
        cudaFuncSetAttribute(attn_mma,    cudaFuncAttributeMaxDynamicSharedMemorySize, AT_SMEM);
        attr_set = true;
    }

#define SYM(p, s) cudaGetSymbolAddress((void**)&p, s)
    __half *x16, *wqkv, *wo, *w1, *w2, *q16, *k16, *v16, *vt, *ctx, *n116, *ff;
    float *t1, *n1, *f2;
    SYM(x16, g_x16); SYM(wqkv, g_wqkv); SYM(wo, g_wo);
    SYM(w1, g_w1); SYM(w2, g_w2);
    SYM(q16, g_q16); SYM(k16, g_k16); SYM(v16, g_v16); SYM(vt, g_vt);
    SYM(ctx, g_ctx); SYM(n116, g_n116); SYM(ff, g_ff);
    SYM(t1, g_t1); SYM(n1, g_n1); SYM(f2, g_f2);
#undef SYM

    detect_mask<<<1, 256>>>(mk);
    convert16<<<512, 256>>>(x, x16, NS_ * D_);
    convert_w<<<1024, 256>>>(Wq, Wk, Wv, Wo, W1, W2, wqkv, wo, w1, w2);

    // QKV fused: seg0 -> Q (scaled), seg1 -> K, seg2 -> V (all fp16)
    gemm_mma<1><<<dim3(2304 / 128, NS_ / 128), 256, GEMM_SMEM>>>(
        x16, wqkv, nullptr, q16, k16, v16, NS_, 2304, D_);

    v_transpose<<<dim3(S_ / 64, N_ * H_), 256>>>(v16, vt);

    attn_mma<<<dim3(S_ / 128, H_, N_), 256, AT_SMEM>>>(q16, k16, vt, mk, ctx);

    gemm_mma<0><<<dim3(D_ / 128, NS_ / 128), 256, GEMM_SMEM>>>(
        ctx, wo, t1, nullptr, nullptr, nullptr, NS_, D_, D_);

    ln_kernel<true><<<NS_, 256>>>(x, t1, lg, lb, n1, n116);

    gemm_mma<2><<<dim3(DFF_ / 128, NS_ / 128), 256, GEMM_SMEM>>>(
        n116, w1, nullptr, ff, nullptr, nullptr, NS_, DFF_, D_);

    gemm_mma<0><<<dim3(D_ / 128, NS_ / 128), 256, GEMM_SMEM>>>(
        ff, w2, f2, nullptr, nullptr, nullptr, NS_, D_, DFF_);

    ln_kernel<false><<<NS_, 256>>>(n1, f2, lg, lb, out, nullptr);
}